// round 2
// baseline (speedup 1.0000x reference)
#include <cuda_runtime.h>
#include <math.h>

#define B_ 2
#define T_ 2048
#define C_ 1024
#define H_ 16
#define DH_ 64
#define BT_ (B_*T_)
#define X_SIZE (BT_*C_)
#define ATT_SIZE (B_*H_*T_*T_)

// Scratch (device globals: allocation-free per harness rules)
__device__ float g_h[BT_ * C_];           // LN output (reused for both LNs)
__device__ float g_qkv[BT_ * 3 * C_];     // fused qkv
__device__ float g_y[BT_ * C_];           // attention output (merged heads)
__device__ float g_x1[BT_ * C_];          // residual after attention
__device__ float g_m[BT_ * 4 * C_];       // GELU output

// ---------------------------------------------------------------------------
// LayerNorm: one block per row, 256 threads, each owns one float4 of C=1024.
// ---------------------------------------------------------------------------
__global__ void __launch_bounds__(256) ln_kernel(const float* __restrict__ x,
                                                 const float* __restrict__ g,
                                                 const float* __restrict__ be,
                                                 float* __restrict__ out)
{
    int row = blockIdx.x;
    int tid = threadIdx.x;
    const float4* xr = (const float4*)(x + (size_t)row * C_);
    float4 v = xr[tid];
    float s  = v.x + v.y + v.z + v.w;
    float ss = v.x * v.x + v.y * v.y + v.z * v.z + v.w * v.w;
    #pragma unroll
    for (int m = 16; m; m >>= 1) {
        s  += __shfl_xor_sync(0xffffffffu, s,  m);
        ss += __shfl_xor_sync(0xffffffffu, ss, m);
    }
    __shared__ float sh_s[8], sh_ss[8];
    if ((tid & 31) == 0) { sh_s[tid >> 5] = s; sh_ss[tid >> 5] = ss; }
    __syncthreads();
    s = 0.f; ss = 0.f;
    #pragma unroll
    for (int i = 0; i < 8; i++) { s += sh_s[i]; ss += sh_ss[i]; }
    float mean = s * (1.f / C_);
    float var  = ss * (1.f / C_) - mean * mean;
    float rstd = rsqrtf(var + 1e-5f);
    float4 gg = ((const float4*)g)[tid];
    float4 bb = ((const float4*)be)[tid];
    float4 o;
    o.x = (v.x - mean) * rstd * gg.x + bb.x;
    o.y = (v.y - mean) * rstd * gg.y + bb.y;
    o.z = (v.z - mean) * rstd * gg.z + bb.z;
    o.w = (v.w - mean) * rstd * gg.w + bb.w;
    ((float4*)(out + (size_t)row * C_))[tid] = o;
}

// ---------------------------------------------------------------------------
// SIMT fp32 GEMM: C[M,N] = A[M,K] @ W[K,N] + bias (+ epilogue)
// 128x128 block tile, BK=8, 256 threads, 8x8 per thread.
// EPI: 0 = bias only, 1 = bias + residual R, 2 = bias + exact GELU
// M,N multiples of 128; K multiple of 8 (all true here).
// ---------------------------------------------------------------------------
template <int EPI>
__global__ void __launch_bounds__(256) gemm_kernel(
    const float* __restrict__ A, const float* __restrict__ W,
    const float* __restrict__ bias, const float* __restrict__ R,
    float* __restrict__ Cout, int M, int N, int K)
{
    __shared__ float As[8][132];   // transposed A tile: As[k][m]
    __shared__ float Bs[8][132];   // Bs[k][n]
    int tid = threadIdx.x;
    int m0 = blockIdx.y * 128, n0 = blockIdx.x * 128;
    int ty = tid >> 4, tx = tid & 15;

    float acc[8][8];
    #pragma unroll
    for (int i = 0; i < 8; i++)
        #pragma unroll
        for (int j = 0; j < 8; j++) acc[i][j] = 0.f;

    int arow = tid >> 1, acol = (tid & 1) * 4;
    int brow = tid >> 5, bcol = (tid & 31) * 4;
    const float* Ap = A + (size_t)(m0 + arow) * K + acol;
    const float* Bp = W + (size_t)brow * N + n0 + bcol;

    for (int k0 = 0; k0 < K; k0 += 8) {
        float4 av = *(const float4*)Ap; Ap += 8;
        float4 bv = *(const float4*)Bp; Bp += (size_t)8 * N;
        As[acol + 0][arow] = av.x;
        As[acol + 1][arow] = av.y;
        As[acol + 2][arow] = av.z;
        As[acol + 3][arow] = av.w;
        *(float4*)&Bs[brow][bcol] = bv;
        __syncthreads();
        #pragma unroll
        for (int kk = 0; kk < 8; kk++) {
            float a[8], b[8];
            *(float4*)(a)     = *(const float4*)&As[kk][ty * 8];
            *(float4*)(a + 4) = *(const float4*)&As[kk][ty * 8 + 4];
            *(float4*)(b)     = *(const float4*)&Bs[kk][tx * 8];
            *(float4*)(b + 4) = *(const float4*)&Bs[kk][tx * 8 + 4];
            #pragma unroll
            for (int i = 0; i < 8; i++)
                #pragma unroll
                for (int j = 0; j < 8; j++)
                    acc[i][j] = fmaf(a[i], b[j], acc[i][j]);
        }
        __syncthreads();
    }

    float bvals[8];
    #pragma unroll
    for (int j = 0; j < 8; j++) bvals[j] = bias[n0 + tx * 8 + j];
    #pragma unroll
    for (int i = 0; i < 8; i++) {
        size_t off = (size_t)(m0 + ty * 8 + i) * N + n0 + tx * 8;
        float o[8];
        #pragma unroll
        for (int j = 0; j < 8; j++) {
            float v = acc[i][j] + bvals[j];
            if (EPI == 2) v = 0.5f * v * (1.0f + erff(v * 0.70710678118654752f));
            if (EPI == 1) v += R[off + j];
            o[j] = v;
        }
        *(float4*)(Cout + off)     = *(float4*)o;
        *(float4*)(Cout + off + 4) = *(float4*)(o + 4);
    }
}

// ---------------------------------------------------------------------------
// Causal attention: grid (qtile=32, b*h=32), block 256 (16x16 threads, 4x4/thread).
// Pass 1: exact online row max/sum over valid k-tiles (kt <= qt).
// Pass 2: recompute S, write normalized probabilities to att (d_out), y += P@V.
// Masked-out tiles (kt > qt) are zero-filled in att.
// ---------------------------------------------------------------------------
__global__ void __launch_bounds__(256) attn_kernel(
    const float* __restrict__ qkv, float* __restrict__ att,
    float* __restrict__ y, int write_att)
{
    extern __shared__ float smem[];
    float* Qt = smem;                 // [64][68]  Qt[d][i]
    float* Kt = Qt + 64 * 68;         // [64][68]  Kt[d][j]
    float* Ps = Kt + 64 * 68;         // [64][68]  Ps[kk][i]
    float* Vs = Ps + 64 * 68;         // [64][68]  Vs[kk][d]

    int qt = blockIdx.x, bh = blockIdx.y;
    int b = bh >> 4, h = bh & 15;
    int tid = threadIdx.x, ty = tid >> 4, tx = tid & 15;
    int q0 = qt * 64;
    const int rowstride = 3 * C_;
    const float* qb = qkv + (size_t)b * T_ * rowstride + h * DH_;
    const float scale = 0.125f;  // 1/sqrt(64)

    // Load Q tile (transposed)
    #pragma unroll
    for (int r = 0; r < 4; r++) {
        int lin = tid + r * 256;
        int i = lin >> 4, dd = (lin & 15) * 4;
        float4 v = *(const float4*)(qb + (size_t)(q0 + i) * rowstride + dd);
        Qt[(dd + 0) * 68 + i] = v.x;
        Qt[(dd + 1) * 68 + i] = v.y;
        Qt[(dd + 2) * 68 + i] = v.z;
        Qt[(dd + 3) * 68 + i] = v.w;
    }
    __syncthreads();

    float mrow[4], lrow[4];
    #pragma unroll
    for (int r = 0; r < 4; r++) { mrow[r] = -1e30f; lrow[r] = 0.f; }

    // ---------------- PASS 1: row statistics ----------------
    for (int kt = 0; kt <= qt; kt++) {
        #pragma unroll
        for (int r = 0; r < 4; r++) {
            int lin = tid + r * 256;
            int i = lin >> 4, dd = (lin & 15) * 4;
            float4 v = *(const float4*)(qb + C_ + (size_t)(kt * 64 + i) * rowstride + dd);
            Kt[(dd + 0) * 68 + i] = v.x;
            Kt[(dd + 1) * 68 + i] = v.y;
            Kt[(dd + 2) * 68 + i] = v.z;
            Kt[(dd + 3) * 68 + i] = v.w;
        }
        __syncthreads();

        float s4[4][4];
        #pragma unroll
        for (int r = 0; r < 4; r++)
            #pragma unroll
            for (int c = 0; c < 4; c++) s4[r][c] = 0.f;
        #pragma unroll 8
        for (int d = 0; d < 64; d++) {
            float4 a  = *(const float4*)&Qt[d * 68 + ty * 4];
            float4 bb = *(const float4*)&Kt[d * 68 + tx * 4];
            float av[4] = {a.x, a.y, a.z, a.w};
            float bvv[4] = {bb.x, bb.y, bb.z, bb.w};
            #pragma unroll
            for (int r = 0; r < 4; r++)
                #pragma unroll
                for (int c = 0; c < 4; c++)
                    s4[r][c] = fmaf(av[r], bvv[c], s4[r][c]);
        }
        bool diag = (kt == qt);
        #pragma unroll
        for (int r = 0; r < 4; r++)
            #pragma unroll
            for (int c = 0; c < 4; c++) {
                float v = s4[r][c] * scale;
                if (diag && (tx * 4 + c) > (ty * 4 + r)) v = -1e30f;
                s4[r][c] = v;
            }
        #pragma unroll
        for (int r = 0; r < 4; r++) {
            float t = fmaxf(fmaxf(s4[r][0], s4[r][1]), fmaxf(s4[r][2], s4[r][3]));
            #pragma unroll
            for (int mk = 1; mk < 16; mk <<= 1)
                t = fmaxf(t, __shfl_xor_sync(0xffffffffu, t, mk));
            float mn = fmaxf(mrow[r], t);
            float sum = expf(s4[r][0] - mn) + expf(s4[r][1] - mn)
                      + expf(s4[r][2] - mn) + expf(s4[r][3] - mn);
            #pragma unroll
            for (int mk = 1; mk < 16; mk <<= 1)
                sum += __shfl_xor_sync(0xffffffffu, sum, mk);
            lrow[r] = lrow[r] * expf(mrow[r] - mn) + sum;
            mrow[r] = mn;
        }
        __syncthreads();
    }

    float linv[4];
    #pragma unroll
    for (int r = 0; r < 4; r++) linv[r] = 1.f / lrow[r];

    float yacc[4][4];
    #pragma unroll
    for (int r = 0; r < 4; r++)
        #pragma unroll
        for (int c = 0; c < 4; c++) yacc[r][c] = 0.f;

    // ---------------- PASS 2: normalized att + y = P@V ----------------
    for (int kt = 0; kt <= qt; kt++) {
        #pragma unroll
        for (int r = 0; r < 4; r++) {
            int lin = tid + r * 256;
            int i = lin >> 4, dd = (lin & 15) * 4;
            float4 v = *(const float4*)(qb + C_ + (size_t)(kt * 64 + i) * rowstride + dd);
            Kt[(dd + 0) * 68 + i] = v.x;
            Kt[(dd + 1) * 68 + i] = v.y;
            Kt[(dd + 2) * 68 + i] = v.z;
            Kt[(dd + 3) * 68 + i] = v.w;
        }
        __syncthreads();

        float s4[4][4];
        #pragma unroll
        for (int r = 0; r < 4; r++)
            #pragma unroll
            for (int c = 0; c < 4; c++) s4[r][c] = 0.f;
        #pragma unroll 8
        for (int d = 0; d < 64; d++) {
            float4 a  = *(const float4*)&Qt[d * 68 + ty * 4];
            float4 bb = *(const float4*)&Kt[d * 68 + tx * 4];
            float av[4] = {a.x, a.y, a.z, a.w};
            float bvv[4] = {bb.x, bb.y, bb.z, bb.w};
            #pragma unroll
            for (int r = 0; r < 4; r++)
                #pragma unroll
                for (int c = 0; c < 4; c++)
                    s4[r][c] = fmaf(av[r], bvv[c], s4[r][c]);
        }
        bool diag = (kt == qt);
        float p[4][4];
        #pragma unroll
        for (int r = 0; r < 4; r++)
            #pragma unroll
            for (int c = 0; c < 4; c++) {
                float pv = expf(s4[r][c] * scale - mrow[r]) * linv[r];
                if (diag && (tx * 4 + c) > (ty * 4 + r)) pv = 0.f;
                p[r][c] = pv;
            }
        if (write_att) {
            #pragma unroll
            for (int r = 0; r < 4; r++) {
                float4 pv = make_float4(p[r][0], p[r][1], p[r][2], p[r][3]);
                *(float4*)(att + ((size_t)bh * T_ + q0 + ty * 4 + r) * T_ + kt * 64 + tx * 4) = pv;
            }
        }
        #pragma unroll
        for (int r = 0; r < 4; r++)
            #pragma unroll
            for (int c = 0; c < 4; c++)
                Ps[(tx * 4 + c) * 68 + ty * 4 + r] = p[r][c];
        // Load V tile
        #pragma unroll
        for (int r = 0; r < 4; r++) {
            int lin = tid + r * 256;
            int i = lin >> 4, dd = (lin & 15) * 4;
            float4 v = *(const float4*)(qb + 2 * C_ + (size_t)(kt * 64 + i) * rowstride + dd);
            *(float4*)&Vs[i * 68 + dd] = v;
        }
        __syncthreads();
        #pragma unroll 8
        for (int kk = 0; kk < 64; kk++) {
            float4 a  = *(const float4*)&Ps[kk * 68 + ty * 4];
            float4 bb = *(const float4*)&Vs[kk * 68 + tx * 4];
            float av[4] = {a.x, a.y, a.z, a.w};
            float bvv[4] = {bb.x, bb.y, bb.z, bb.w};
            #pragma unroll
            for (int r = 0; r < 4; r++)
                #pragma unroll
                for (int c = 0; c < 4; c++)
                    yacc[r][c] = fmaf(av[r], bvv[c], yacc[r][c]);
        }
        __syncthreads();
    }

    // Zero-fill causal upper triangle of att
    if (write_att) {
        float4 z = make_float4(0.f, 0.f, 0.f, 0.f);
        for (int kt = qt + 1; kt < T_ / 64; kt++) {
            #pragma unroll
            for (int r = 0; r < 4; r++) {
                int lin = tid + r * 256;
                int i = lin >> 4, jj = (lin & 15) * 4;
                *(float4*)(att + ((size_t)bh * T_ + q0 + i) * T_ + kt * 64 + jj) = z;
            }
        }
    }

    // Write y (merged-head layout: [b*T + t, h*DH + d])
    #pragma unroll
    for (int r = 0; r < 4; r++) {
        float4 v = make_float4(yacc[r][0], yacc[r][1], yacc[r][2], yacc[r][3]);
        *(float4*)(y + ((size_t)b * T_ + q0 + ty * 4 + r) * C_ + h * DH_ + tx * 4) = v;
    }
}

// ---------------------------------------------------------------------------
extern "C" void kernel_launch(void* const* d_in, const int* in_sizes, int n_in,
                              void* d_out, int out_size)
{
    (void)in_sizes; (void)n_in;
    const float* x      = (const float*)d_in[0];
    const float* W_attn = (const float*)d_in[1];
    const float* b_attn = (const float*)d_in[2];
    const float* W_o    = (const float*)d_in[3];
    const float* b_o    = (const float*)d_in[4];
    const float* W_fc   = (const float*)d_in[5];
    const float* b_fc   = (const float*)d_in[6];
    const float* W_fc2  = (const float*)d_in[7];
    const float* b_fc2  = (const float*)d_in[8];
    const float* g1     = (const float*)d_in[9];
    const float* be1    = (const float*)d_in[10];
    const float* g2     = (const float*)d_in[11];
    const float* be2    = (const float*)d_in[12];
    float* out = (float*)d_out;

    float *h, *qkv, *y, *x1, *m;
    cudaGetSymbolAddress((void**)&h,   g_h);
    cudaGetSymbolAddress((void**)&qkv, g_qkv);
    cudaGetSymbolAddress((void**)&y,   g_y);
    cudaGetSymbolAddress((void**)&x1,  g_x1);
    cudaGetSymbolAddress((void**)&m,   g_m);

    int write_att = (out_size >= X_SIZE + ATT_SIZE) ? 1 : 0;
    float* att = out + X_SIZE;

    const int SMEM_ATTN = 4 * 64 * 68 * sizeof(float);  // 69632 B
    cudaFuncSetAttribute(attn_kernel, cudaFuncAttributeMaxDynamicSharedMemorySize, SMEM_ATTN);

    // 1. h = LN1(x)
    ln_kernel<<<BT_, 256>>>(x, g1, be1, h);
    // 2. qkv = h @ W_attn + b_attn
    gemm_kernel<0><<<dim3(3 * C_ / 128, BT_ / 128), 256>>>(h, W_attn, b_attn, nullptr, qkv, BT_, 3 * C_, C_);
    // 3. attention -> att (d_out) + y
    attn_kernel<<<dim3(T_ / 64, B_ * H_), 256, SMEM_ATTN>>>(qkv, att, y, write_att);
    // 4. x1 = x + y @ W_o + b_o
    gemm_kernel<1><<<dim3(C_ / 128, BT_ / 128), 256>>>(y, W_o, b_o, x, x1, BT_, C_, C_);
    // 5. h = LN2(x1)
    ln_kernel<<<BT_, 256>>>(x1, g2, be2, h);
    // 6. m = gelu(h @ W_fc + b_fc)
    gemm_kernel<2><<<dim3(4 * C_ / 128, BT_ / 128), 256>>>(h, W_fc, b_fc, nullptr, m, BT_, 4 * C_, C_);
    // 7. out_x = x1 + m @ W_fc2 + b_fc2
    gemm_kernel<1><<<dim3(C_ / 128, BT_ / 128), 256>>>(m, W_fc2, b_fc2, x1, out, BT_, C_, 4 * C_);
}

// round 3
// speedup vs baseline: 1.6653x; 1.6653x over previous
#include <cuda_runtime.h>
#include <math.h>
#include <stdint.h>

#define B_ 2
#define T_ 2048
#define C_ 1024
#define H_ 16
#define DH_ 64
#define BT_ (B_*T_)
#define X_SIZE (BT_*C_)
#define ATT_SIZE (B_*H_*T_*T_)

// Scratch (device globals: allocation-free per harness rules)
__device__ float g_h[BT_ * C_];
__device__ float g_qkv[BT_ * 3 * C_];
__device__ float g_y[BT_ * C_];
__device__ float g_x1[BT_ * C_];
__device__ float g_m[BT_ * 4 * C_];

// ---------------------------------------------------------------------------
// LayerNorm: one block per row, 256 threads, each owns one float4 of C=1024.
// ---------------------------------------------------------------------------
__global__ void __launch_bounds__(256) ln_kernel(const float* __restrict__ x,
                                                 const float* __restrict__ g,
                                                 const float* __restrict__ be,
                                                 float* __restrict__ out)
{
    int row = blockIdx.x;
    int tid = threadIdx.x;
    const float4* xr = (const float4*)(x + (size_t)row * C_);
    float4 v = xr[tid];
    float s  = v.x + v.y + v.z + v.w;
    float ss = v.x * v.x + v.y * v.y + v.z * v.z + v.w * v.w;
    #pragma unroll
    for (int m = 16; m; m >>= 1) {
        s  += __shfl_xor_sync(0xffffffffu, s,  m);
        ss += __shfl_xor_sync(0xffffffffu, ss, m);
    }
    __shared__ float sh_s[8], sh_ss[8];
    if ((tid & 31) == 0) { sh_s[tid >> 5] = s; sh_ss[tid >> 5] = ss; }
    __syncthreads();
    s = 0.f; ss = 0.f;
    #pragma unroll
    for (int i = 0; i < 8; i++) { s += sh_s[i]; ss += sh_ss[i]; }
    float mean = s * (1.f / C_);
    float var  = ss * (1.f / C_) - mean * mean;
    float rstd = rsqrtf(var + 1e-5f);
    float4 gg = ((const float4*)g)[tid];
    float4 bb = ((const float4*)be)[tid];
    float4 o;
    o.x = (v.x - mean) * rstd * gg.x + bb.x;
    o.y = (v.y - mean) * rstd * gg.y + bb.y;
    o.z = (v.z - mean) * rstd * gg.z + bb.z;
    o.w = (v.w - mean) * rstd * gg.w + bb.w;
    ((float4*)(out + (size_t)row * C_))[tid] = o;
}

// ---------------------------------------------------------------------------
// tf32 tensor-core GEMM: C[M,N] = A[M,K] @ W[K,N] + bias (+ epilogue)
// 128x128 block tile, BK=16, 256 threads (8 warps, 2x4), warp tile 64x32.
// mma.sync.aligned.m16n8k8.row.col.f32.tf32.tf32.f32
// EPI: 0 = bias, 1 = bias + residual R, 2 = bias + exact GELU
// ---------------------------------------------------------------------------
__device__ __forceinline__ uint32_t f2tf(float f) {
    uint32_t u;
    asm("cvt.rna.tf32.f32 %0, %1;" : "=r"(u) : "f"(f));
    return u;
}

__device__ __forceinline__ void mma_tf32(float (&d)[4], const uint32_t (&a)[4],
                                         const uint32_t (&b)[2]) {
    asm volatile(
        "mma.sync.aligned.m16n8k8.row.col.f32.tf32.tf32.f32 "
        "{%0,%1,%2,%3}, {%4,%5,%6,%7}, {%8,%9}, {%0,%1,%2,%3};"
        : "+f"(d[0]), "+f"(d[1]), "+f"(d[2]), "+f"(d[3])
        : "r"(a[0]), "r"(a[1]), "r"(a[2]), "r"(a[3]), "r"(b[0]), "r"(b[1]));
}

#define ASW(k) (((k) & 8) << 1)   // XOR swizzle on m index by k bit3 (=> ^16)

template <int EPI>
__global__ void __launch_bounds__(256) gemm_tc(
    const float* __restrict__ A, const float* __restrict__ W,
    const float* __restrict__ bias, const float* __restrict__ R,
    float* __restrict__ Cout, int M, int N, int K)
{
    __shared__ uint32_t sA[16 * 136];   // [k][m^swz], pad 136 (bank stride 8)
    __shared__ uint32_t sB[16 * 136];   // [k][n]

    const int tid  = threadIdx.x;
    const int lane = tid & 31;
    const int wid  = tid >> 5;
    const int wm   = (wid >> 2) * 64;   // warp m offset in tile
    const int wn   = (wid & 3) * 32;    // warp n offset in tile
    const int m0 = blockIdx.y * 128, n0 = blockIdx.x * 128;

    // A load mapping: coalesced along k. aRow 0..127, aCol in {0,8}
    const int aRow  = tid >> 1;
    const int aCol  = (tid & 1) * 8;
    // B load mapping: bRow 0..15 (k), bCol4 0..15 (float4 index in n)
    const int bRow  = tid >> 4;
    const int bCol4 = tid & 15;

    const float* Ap = A + (size_t)(m0 + aRow) * K + aCol;
    const float* Bp = W + (size_t)bRow * N + n0 + bCol4 * 4;

    float acc[4][4][4];
    #pragma unroll
    for (int mt = 0; mt < 4; mt++)
        #pragma unroll
        for (int nt = 0; nt < 4; nt++)
            #pragma unroll
            for (int i = 0; i < 4; i++) acc[mt][nt][i] = 0.f;

    const int KT = K >> 4;

    // prefetch tile 0
    float4 pa0 = *(const float4*)Ap;
    float4 pa1 = *(const float4*)(Ap + 4);
    float4 pb0 = *(const float4*)Bp;
    float4 pb1 = *(const float4*)(Bp + 64);

    for (int kt = 0; kt < KT; ++kt) {
        // ---- store prefetched tile to smem (tf32-converted) ----
        {
            float va[8];
            *(float4*)(va)     = pa0;
            *(float4*)(va + 4) = pa1;
            #pragma unroll
            for (int j = 0; j < 8; j++) {
                int k = aCol + j;
                sA[k * 136 + (aRow ^ ASW(k))] = f2tf(va[j]);
            }
            float vb[8];
            *(float4*)(vb)     = pb0;
            *(float4*)(vb + 4) = pb1;
            uint4 u0, u1;
            u0.x = f2tf(vb[0]); u0.y = f2tf(vb[1]); u0.z = f2tf(vb[2]); u0.w = f2tf(vb[3]);
            u1.x = f2tf(vb[4]); u1.y = f2tf(vb[5]); u1.z = f2tf(vb[6]); u1.w = f2tf(vb[7]);
            *(uint4*)&sB[bRow * 136 + bCol4 * 4]      = u0;
            *(uint4*)&sB[bRow * 136 + bCol4 * 4 + 64] = u1;
        }
        __syncthreads();

        // ---- prefetch next tile ----
        if (kt + 1 < KT) {
            const float* Apn = Ap + (kt + 1) * 16;
            const float* Bpn = Bp + (size_t)(kt + 1) * 16 * N;
            pa0 = *(const float4*)Apn;
            pa1 = *(const float4*)(Apn + 4);
            pb0 = *(const float4*)Bpn;
            pb1 = *(const float4*)(Bpn + 64);
        }

        // ---- compute ----
        #pragma unroll
        for (int ks = 0; ks < 16; ks += 8) {
            uint32_t af[4][4];
            const int r  = lane >> 2;
            const int cc = lane & 3;
            #pragma unroll
            for (int mt = 0; mt < 4; mt++) {
                int mrow = wm + mt * 16 + r;
                int k0a = ks + cc, k1a = ks + cc + 4;
                af[mt][0] = sA[k0a * 136 + ((mrow)     ^ ASW(k0a))];
                af[mt][1] = sA[k0a * 136 + ((mrow + 8) ^ ASW(k0a))];
                af[mt][2] = sA[k1a * 136 + ((mrow)     ^ ASW(k1a))];
                af[mt][3] = sA[k1a * 136 + ((mrow + 8) ^ ASW(k1a))];
            }
            uint32_t bf[4][2];
            #pragma unroll
            for (int nt = 0; nt < 4; nt++) {
                int ncol = wn + nt * 8 + (lane >> 2);
                bf[nt][0] = sB[(ks + (lane & 3)) * 136 + ncol];
                bf[nt][1] = sB[(ks + 4 + (lane & 3)) * 136 + ncol];
            }
            #pragma unroll
            for (int mt = 0; mt < 4; mt++)
                #pragma unroll
                for (int nt = 0; nt < 4; nt++)
                    mma_tf32(acc[mt][nt], af[mt], bf[nt]);
        }
        __syncthreads();
    }

    // ---- epilogue ----
    #pragma unroll
    for (int nt = 0; nt < 4; nt++) {
        int col = n0 + wn + nt * 8 + ((lane & 3) << 1);
        float bx = bias[col], by = bias[col + 1];
        #pragma unroll
        for (int mt = 0; mt < 4; mt++) {
            int row0 = m0 + wm + mt * 16 + (lane >> 2);
            #pragma unroll
            for (int half = 0; half < 2; half++) {
                int row = row0 + half * 8;
                float vx = acc[mt][nt][half * 2 + 0] + bx;
                float vy = acc[mt][nt][half * 2 + 1] + by;
                if (EPI == 2) {
                    vx = 0.5f * vx * (1.0f + erff(vx * 0.70710678118654752f));
                    vy = 0.5f * vy * (1.0f + erff(vy * 0.70710678118654752f));
                }
                size_t off = (size_t)row * N + col;
                if (EPI == 1) {
                    vx += R[off];
                    vy += R[off + 1];
                }
                *(float2*)(Cout + off) = make_float2(vx, vy);
            }
        }
    }
}

// ---------------------------------------------------------------------------
// Causal attention (unchanged from R2): grid (qtile=32, b*h=32), block 256.
// ---------------------------------------------------------------------------
__global__ void __launch_bounds__(256) attn_kernel(
    const float* __restrict__ qkv, float* __restrict__ att,
    float* __restrict__ y, int write_att)
{
    extern __shared__ float smem[];
    float* Qt = smem;
    float* Kt = Qt + 64 * 68;
    float* Ps = Kt + 64 * 68;
    float* Vs = Ps + 64 * 68;

    int qt = blockIdx.x, bh = blockIdx.y;
    int b = bh >> 4, h = bh & 15;
    int tid = threadIdx.x, ty = tid >> 4, tx = tid & 15;
    int q0 = qt * 64;
    const int rowstride = 3 * C_;
    const float* qb = qkv + (size_t)b * T_ * rowstride + h * DH_;
    const float scale = 0.125f;

    #pragma unroll
    for (int r = 0; r < 4; r++) {
        int lin = tid + r * 256;
        int i = lin >> 4, dd = (lin & 15) * 4;
        float4 v = *(const float4*)(qb + (size_t)(q0 + i) * rowstride + dd);
        Qt[(dd + 0) * 68 + i] = v.x;
        Qt[(dd + 1) * 68 + i] = v.y;
        Qt[(dd + 2) * 68 + i] = v.z;
        Qt[(dd + 3) * 68 + i] = v.w;
    }
    __syncthreads();

    float mrow[4], lrow[4];
    #pragma unroll
    for (int r = 0; r < 4; r++) { mrow[r] = -1e30f; lrow[r] = 0.f; }

    for (int kt = 0; kt <= qt; kt++) {
        #pragma unroll
        for (int r = 0; r < 4; r++) {
            int lin = tid + r * 256;
            int i = lin >> 4, dd = (lin & 15) * 4;
            float4 v = *(const float4*)(qb + C_ + (size_t)(kt * 64 + i) * rowstride + dd);
            Kt[(dd + 0) * 68 + i] = v.x;
            Kt[(dd + 1) * 68 + i] = v.y;
            Kt[(dd + 2) * 68 + i] = v.z;
            Kt[(dd + 3) * 68 + i] = v.w;
        }
        __syncthreads();

        float s4[4][4];
        #pragma unroll
        for (int r = 0; r < 4; r++)
            #pragma unroll
            for (int c = 0; c < 4; c++) s4[r][c] = 0.f;
        #pragma unroll 8
        for (int d = 0; d < 64; d++) {
            float4 a  = *(const float4*)&Qt[d * 68 + ty * 4];
            float4 bb = *(const float4*)&Kt[d * 68 + tx * 4];
            float av[4] = {a.x, a.y, a.z, a.w};
            float bvv[4] = {bb.x, bb.y, bb.z, bb.w};
            #pragma unroll
            for (int r = 0; r < 4; r++)
                #pragma unroll
                for (int c = 0; c < 4; c++)
                    s4[r][c] = fmaf(av[r], bvv[c], s4[r][c]);
        }
        bool diag = (kt == qt);
        #pragma unroll
        for (int r = 0; r < 4; r++)
            #pragma unroll
            for (int c = 0; c < 4; c++) {
                float v = s4[r][c] * scale;
                if (diag && (tx * 4 + c) > (ty * 4 + r)) v = -1e30f;
                s4[r][c] = v;
            }
        #pragma unroll
        for (int r = 0; r < 4; r++) {
            float t = fmaxf(fmaxf(s4[r][0], s4[r][1]), fmaxf(s4[r][2], s4[r][3]));
            #pragma unroll
            for (int mk = 1; mk < 16; mk <<= 1)
                t = fmaxf(t, __shfl_xor_sync(0xffffffffu, t, mk));
            float mn = fmaxf(mrow[r], t);
            float sum = expf(s4[r][0] - mn) + expf(s4[r][1] - mn)
                      + expf(s4[r][2] - mn) + expf(s4[r][3] - mn);
            #pragma unroll
            for (int mk = 1; mk < 16; mk <<= 1)
                sum += __shfl_xor_sync(0xffffffffu, sum, mk);
            lrow[r] = lrow[r] * expf(mrow[r] - mn) + sum;
            mrow[r] = mn;
        }
        __syncthreads();
    }

    float linv[4];
    #pragma unroll
    for (int r = 0; r < 4; r++) linv[r] = 1.f / lrow[r];

    float yacc[4][4];
    #pragma unroll
    for (int r = 0; r < 4; r++)
        #pragma unroll
        for (int c = 0; c < 4; c++) yacc[r][c] = 0.f;

    for (int kt = 0; kt <= qt; kt++) {
        #pragma unroll
        for (int r = 0; r < 4; r++) {
            int lin = tid + r * 256;
            int i = lin >> 4, dd = (lin & 15) * 4;
            float4 v = *(const float4*)(qb + C_ + (size_t)(kt * 64 + i) * rowstride + dd);
            Kt[(dd + 0) * 68 + i] = v.x;
            Kt[(dd + 1) * 68 + i] = v.y;
            Kt[(dd + 2) * 68 + i] = v.z;
            Kt[(dd + 3) * 68 + i] = v.w;
        }
        __syncthreads();

        float s4[4][4];
        #pragma unroll
        for (int r = 0; r < 4; r++)
            #pragma unroll
            for (int c = 0; c < 4; c++) s4[r][c] = 0.f;
        #pragma unroll 8
        for (int d = 0; d < 64; d++) {
            float4 a  = *(const float4*)&Qt[d * 68 + ty * 4];
            float4 bb = *(const float4*)&Kt[d * 68 + tx * 4];
            float av[4] = {a.x, a.y, a.z, a.w};
            float bvv[4] = {bb.x, bb.y, bb.z, bb.w};
            #pragma unroll
            for (int r = 0; r < 4; r++)
                #pragma unroll
                for (int c = 0; c < 4; c++)
                    s4[r][c] = fmaf(av[r], bvv[c], s4[r][c]);
        }
        bool diag = (kt == qt);
        float p[4][4];
        #pragma unroll
        for (int r = 0; r < 4; r++)
            #pragma unroll
            for (int c = 0; c < 4; c++) {
                float pv = expf(s4[r][c] * scale - mrow[r]) * linv[r];
                if (diag && (tx * 4 + c) > (ty * 4 + r)) pv = 0.f;
                p[r][c] = pv;
            }
        if (write_att) {
            #pragma unroll
            for (int r = 0; r < 4; r++) {
                float4 pv = make_float4(p[r][0], p[r][1], p[r][2], p[r][3]);
                *(float4*)(att + ((size_t)bh * T_ + q0 + ty * 4 + r) * T_ + kt * 64 + tx * 4) = pv;
            }
        }
        #pragma unroll
        for (int r = 0; r < 4; r++)
            #pragma unroll
            for (int c = 0; c < 4; c++)
                Ps[(tx * 4 + c) * 68 + ty * 4 + r] = p[r][c];
        #pragma unroll
        for (int r = 0; r < 4; r++) {
            int lin = tid + r * 256;
            int i = lin >> 4, dd = (lin & 15) * 4;
            float4 v = *(const float4*)(qb + 2 * C_ + (size_t)(kt * 64 + i) * rowstride + dd);
            *(float4*)&Vs[i * 68 + dd] = v;
        }
        __syncthreads();
        #pragma unroll 8
        for (int kk = 0; kk < 64; kk++) {
            float4 a  = *(const float4*)&Ps[kk * 68 + ty * 4];
            float4 bb = *(const float4*)&Vs[kk * 68 + tx * 4];
            float av[4] = {a.x, a.y, a.z, a.w};
            float bvv[4] = {bb.x, bb.y, bb.z, bb.w};
            #pragma unroll
            for (int r = 0; r < 4; r++)
                #pragma unroll
                for (int c = 0; c < 4; c++)
                    yacc[r][c] = fmaf(av[r], bvv[c], yacc[r][c]);
        }
        __syncthreads();
    }

    if (write_att) {
        float4 z = make_float4(0.f, 0.f, 0.f, 0.f);
        for (int kt = qt + 1; kt < T_ / 64; kt++) {
            #pragma unroll
            for (int r = 0; r < 4; r++) {
                int lin = tid + r * 256;
                int i = lin >> 4, jj = (lin & 15) * 4;
                *(float4*)(att + ((size_t)bh * T_ + q0 + i) * T_ + kt * 64 + jj) = z;
            }
        }
    }

    #pragma unroll
    for (int r = 0; r < 4; r++) {
        float4 v = make_float4(yacc[r][0], yacc[r][1], yacc[r][2], yacc[r][3]);
        *(float4*)(y + ((size_t)b * T_ + q0 + ty * 4 + r) * C_ + h * DH_ + tx * 4) = v;
    }
}

// ---------------------------------------------------------------------------
extern "C" void kernel_launch(void* const* d_in, const int* in_sizes, int n_in,
                              void* d_out, int out_size)
{
    (void)in_sizes; (void)n_in;
    const float* x      = (const float*)d_in[0];
    const float* W_attn = (const float*)d_in[1];
    const float* b_attn = (const float*)d_in[2];
    const float* W_o    = (const float*)d_in[3];
    const float* b_o    = (const float*)d_in[4];
    const float* W_fc   = (const float*)d_in[5];
    const float* b_fc   = (const float*)d_in[6];
    const float* W_fc2  = (const float*)d_in[7];
    const float* b_fc2  = (const float*)d_in[8];
    const float* g1     = (const float*)d_in[9];
    const float* be1    = (const float*)d_in[10];
    const float* g2     = (const float*)d_in[11];
    const float* be2    = (const float*)d_in[12];
    float* out = (float*)d_out;

    float *h, *qkv, *y, *x1, *m;
    cudaGetSymbolAddress((void**)&h,   g_h);
    cudaGetSymbolAddress((void**)&qkv, g_qkv);
    cudaGetSymbolAddress((void**)&y,   g_y);
    cudaGetSymbolAddress((void**)&x1,  g_x1);
    cudaGetSymbolAddress((void**)&m,   g_m);

    int write_att = (out_size >= X_SIZE + ATT_SIZE) ? 1 : 0;
    float* att = out + X_SIZE;

    const int SMEM_ATTN = 4 * 64 * 68 * sizeof(float);
    cudaFuncSetAttribute(attn_kernel, cudaFuncAttributeMaxDynamicSharedMemorySize, SMEM_ATTN);

    // 1. h = LN1(x)
    ln_kernel<<<BT_, 256>>>(x, g1, be1, h);
    // 2. qkv = h @ W_attn + b_attn
    gemm_tc<0><<<dim3(3 * C_ / 128, BT_ / 128), 256>>>(h, W_attn, b_attn, nullptr, qkv, BT_, 3 * C_, C_);
    // 3. attention -> att (d_out) + y
    attn_kernel<<<dim3(T_ / 64, B_ * H_), 256, SMEM_ATTN>>>(qkv, att, y, write_att);
    // 4. x1 = x + y @ W_o + b_o
    gemm_tc<1><<<dim3(C_ / 128, BT_ / 128), 256>>>(y, W_o, b_o, x, x1, BT_, C_, C_);
    // 5. h = LN2(x1)
    ln_kernel<<<BT_, 256>>>(x1, g2, be2, h);
    // 6. m = gelu(h @ W_fc + b_fc)
    gemm_tc<2><<<dim3(4 * C_ / 128, BT_ / 128), 256>>>(h, W_fc, b_fc, nullptr, m, BT_, 4 * C_, C_);
    // 7. out_x = x1 + m @ W_fc2 + b_fc2
    gemm_tc<1><<<dim3(C_ / 128, BT_ / 128), 256>>>(m, W_fc2, b_fc2, x1, out, BT_, C_, 4 * C_);
}

// round 4
// speedup vs baseline: 2.6022x; 1.5626x over previous
#include <cuda_runtime.h>
#include <math.h>
#include <stdint.h>

#define B_ 2
#define T_ 2048
#define C_ 1024
#define H_ 16
#define DH_ 64
#define BT_ (B_*T_)
#define X_SIZE (BT_*C_)
#define ATT_SIZE (B_*H_*T_*T_)

// Scratch (device globals: allocation-free per harness rules)
__device__ float g_h[BT_ * C_];
__device__ float g_qkv[BT_ * 3 * C_];
__device__ float g_y[BT_ * C_];
__device__ float g_x1[BT_ * C_];
__device__ float g_m[BT_ * 4 * C_];

// ---------------------------------------------------------------------------
__device__ __forceinline__ uint32_t f2tf(float f) {
    uint32_t u;
    asm("cvt.rna.tf32.f32 %0, %1;" : "=r"(u) : "f"(f));
    return u;
}

__device__ __forceinline__ void mma_tf32(float (&d)[4], const uint32_t (&a)[4],
                                         const uint32_t (&b)[2]) {
    asm volatile(
        "mma.sync.aligned.m16n8k8.row.col.f32.tf32.tf32.f32 "
        "{%0,%1,%2,%3}, {%4,%5,%6,%7}, {%8,%9}, {%0,%1,%2,%3};"
        : "+f"(d[0]), "+f"(d[1]), "+f"(d[2]), "+f"(d[3])
        : "r"(a[0]), "r"(a[1]), "r"(a[2]), "r"(a[3]), "r"(b[0]), "r"(b[1]));
}

// ---------------------------------------------------------------------------
// LayerNorm: one block per row, 256 threads.
// ---------------------------------------------------------------------------
__global__ void __launch_bounds__(256) ln_kernel(const float* __restrict__ x,
                                                 const float* __restrict__ g,
                                                 const float* __restrict__ be,
                                                 float* __restrict__ out)
{
    int row = blockIdx.x;
    int tid = threadIdx.x;
    const float4* xr = (const float4*)(x + (size_t)row * C_);
    float4 v = xr[tid];
    float s  = v.x + v.y + v.z + v.w;
    float ss = v.x * v.x + v.y * v.y + v.z * v.z + v.w * v.w;
    #pragma unroll
    for (int m = 16; m; m >>= 1) {
        s  += __shfl_xor_sync(0xffffffffu, s,  m);
        ss += __shfl_xor_sync(0xffffffffu, ss, m);
    }
    __shared__ float sh_s[8], sh_ss[8];
    if ((tid & 31) == 0) { sh_s[tid >> 5] = s; sh_ss[tid >> 5] = ss; }
    __syncthreads();
    s = 0.f; ss = 0.f;
    #pragma unroll
    for (int i = 0; i < 8; i++) { s += sh_s[i]; ss += sh_ss[i]; }
    float mean = s * (1.f / C_);
    float var  = ss * (1.f / C_) - mean * mean;
    float rstd = rsqrtf(var + 1e-5f);
    float4 gg = ((const float4*)g)[tid];
    float4 bb = ((const float4*)be)[tid];
    float4 o;
    o.x = (v.x - mean) * rstd * gg.x + bb.x;
    o.y = (v.y - mean) * rstd * gg.y + bb.y;
    o.z = (v.z - mean) * rstd * gg.z + bb.z;
    o.w = (v.w - mean) * rstd * gg.w + bb.w;
    ((float4*)(out + (size_t)row * C_))[tid] = o;
}

// ---------------------------------------------------------------------------
// tf32 tensor-core GEMM, 2-stage double-buffered smem, 2 CTAs/SM.
// 128x128 tile, BK=16, 256 threads (8 warps 2x4), warp tile 64x32.
// ---------------------------------------------------------------------------
#define ASW(k) (((k) & 8) << 1)
#define GSTG (16 * 136)

template <int EPI>
__global__ void __launch_bounds__(256, 2) gemm_tc(
    const float* __restrict__ A, const float* __restrict__ W,
    const float* __restrict__ bias, const float* __restrict__ R,
    float* __restrict__ Cout, int M, int N, int K)
{
    extern __shared__ uint32_t dsm[];
    uint32_t* sA = dsm;             // [2][16*136]
    uint32_t* sB = dsm + 2 * GSTG;  // [2][16*136]

    const int tid  = threadIdx.x;
    const int lane = tid & 31;
    const int wid  = tid >> 5;
    const int wm   = (wid >> 2) * 64;
    const int wn   = (wid & 3) * 32;
    const int m0 = blockIdx.y * 128, n0 = blockIdx.x * 128;

    const int aRow  = tid >> 1;
    const int aCol  = (tid & 1) * 8;
    const int bRow  = tid >> 4;
    const int bCol4 = tid & 15;

    const float* Ap = A + (size_t)(m0 + aRow) * K + aCol;
    const float* Bp = W + (size_t)bRow * N + n0 + bCol4 * 4;

    float acc[4][4][4];
    #pragma unroll
    for (int mt = 0; mt < 4; mt++)
        #pragma unroll
        for (int nt = 0; nt < 4; nt++)
            #pragma unroll
            for (int i = 0; i < 4; i++) acc[mt][nt][i] = 0.f;

    const int KT = K >> 4;

    float4 pa0, pa1, pb0, pb1;
    pa0 = *(const float4*)Ap;
    pa1 = *(const float4*)(Ap + 4);
    pb0 = *(const float4*)Bp;
    pb1 = *(const float4*)(Bp + 64);

    // store stage 0
    {
        float va[8];
        *(float4*)(va) = pa0; *(float4*)(va + 4) = pa1;
        #pragma unroll
        for (int j = 0; j < 8; j++) {
            int k = aCol + j;
            sA[k * 136 + (aRow ^ ASW(k))] = f2tf(va[j]);
        }
        float vb[8];
        *(float4*)(vb) = pb0; *(float4*)(vb + 4) = pb1;
        uint4 u0, u1;
        u0.x = f2tf(vb[0]); u0.y = f2tf(vb[1]); u0.z = f2tf(vb[2]); u0.w = f2tf(vb[3]);
        u1.x = f2tf(vb[4]); u1.y = f2tf(vb[5]); u1.z = f2tf(vb[6]); u1.w = f2tf(vb[7]);
        *(uint4*)&sB[bRow * 136 + bCol4 * 4]      = u0;
        *(uint4*)&sB[bRow * 136 + bCol4 * 4 + 64] = u1;
    }
    __syncthreads();

    for (int kt = 0; kt < KT; ++kt) {
        if (kt + 1 < KT) {
            const float* Apn = Ap + (kt + 1) * 16;
            const float* Bpn = Bp + (size_t)(kt + 1) * 16 * N;
            pa0 = *(const float4*)Apn;
            pa1 = *(const float4*)(Apn + 4);
            pb0 = *(const float4*)Bpn;
            pb1 = *(const float4*)(Bpn + 64);
        }
        const uint32_t* sa = sA + (kt & 1) * GSTG;
        const uint32_t* sb = sB + (kt & 1) * GSTG;
        #pragma unroll
        for (int ks = 0; ks < 16; ks += 8) {
            uint32_t af[4][4];
            const int r  = lane >> 2;
            const int cc = lane & 3;
            #pragma unroll
            for (int mt = 0; mt < 4; mt++) {
                int mrow = wm + mt * 16 + r;
                int k0a = ks + cc, k1a = ks + cc + 4;
                af[mt][0] = sa[k0a * 136 + ((mrow)     ^ ASW(k0a))];
                af[mt][1] = sa[k0a * 136 + ((mrow + 8) ^ ASW(k0a))];
                af[mt][2] = sa[k1a * 136 + ((mrow)     ^ ASW(k1a))];
                af[mt][3] = sa[k1a * 136 + ((mrow + 8) ^ ASW(k1a))];
            }
            uint32_t bf[4][2];
            #pragma unroll
            for (int nt = 0; nt < 4; nt++) {
                int ncol = wn + nt * 8 + (lane >> 2);
                bf[nt][0] = sb[(ks + (lane & 3)) * 136 + ncol];
                bf[nt][1] = sb[(ks + 4 + (lane & 3)) * 136 + ncol];
            }
            #pragma unroll
            for (int mt = 0; mt < 4; mt++)
                #pragma unroll
                for (int nt = 0; nt < 4; nt++)
                    mma_tf32(acc[mt][nt], af[mt], bf[nt]);
        }
        if (kt + 1 < KT) {
            uint32_t* da = sA + ((kt + 1) & 1) * GSTG;
            uint32_t* db = sB + ((kt + 1) & 1) * GSTG;
            float va[8];
            *(float4*)(va) = pa0; *(float4*)(va + 4) = pa1;
            #pragma unroll
            for (int j = 0; j < 8; j++) {
                int k = aCol + j;
                da[k * 136 + (aRow ^ ASW(k))] = f2tf(va[j]);
            }
            float vb[8];
            *(float4*)(vb) = pb0; *(float4*)(vb + 4) = pb1;
            uint4 u0, u1;
            u0.x = f2tf(vb[0]); u0.y = f2tf(vb[1]); u0.z = f2tf(vb[2]); u0.w = f2tf(vb[3]);
            u1.x = f2tf(vb[4]); u1.y = f2tf(vb[5]); u1.z = f2tf(vb[6]); u1.w = f2tf(vb[7]);
            *(uint4*)&db[bRow * 136 + bCol4 * 4]      = u0;
            *(uint4*)&db[bRow * 136 + bCol4 * 4 + 64] = u1;
            __syncthreads();
        }
    }

    // ---- epilogue ----
    #pragma unroll
    for (int nt = 0; nt < 4; nt++) {
        int col = n0 + wn + nt * 8 + ((lane & 3) << 1);
        float bx = bias[col], by = bias[col + 1];
        #pragma unroll
        for (int mt = 0; mt < 4; mt++) {
            int row0 = m0 + wm + mt * 16 + (lane >> 2);
            #pragma unroll
            for (int half = 0; half < 2; half++) {
                int row = row0 + half * 8;
                float vx = acc[mt][nt][half * 2 + 0] + bx;
                float vy = acc[mt][nt][half * 2 + 1] + by;
                if (EPI == 2) {
                    vx = 0.5f * vx * (1.0f + erff(vx * 0.70710678118654752f));
                    vy = 0.5f * vy * (1.0f + erff(vy * 0.70710678118654752f));
                }
                size_t off = (size_t)row * N + col;
                if (EPI == 1) {
                    vx += R[off];
                    vy += R[off + 1];
                }
                *(float2*)(Cout + off) = make_float2(vx, vy);
            }
        }
    }
}

// ---------------------------------------------------------------------------
// Tensor-core causal flash attention with exact 2-pass softmax.
// Block: 128 threads (4 warps), tile 64q x 64k, DH=64.
// Warp w owns q rows [w*16, w*16+16). All mma operands tf32 (rna).
// ---------------------------------------------------------------------------
#define PAD 68

__global__ void __launch_bounds__(128) attn_tc(
    const float* __restrict__ qkv, float* __restrict__ att,
    float* __restrict__ y, int write_att)
{
    extern __shared__ uint32_t sm[];
    uint32_t* Qs = sm;               // [64][68]
    uint32_t* Ks = Qs + 64 * PAD;
    uint32_t* Vs = Ks + 64 * PAD;
    uint32_t* Ps = Vs + 64 * PAD;

    const int qt = blockIdx.x, bh = blockIdx.y;
    const int b = bh >> 4, h = bh & 15;
    const int tid = threadIdx.x;
    const int lane = tid & 31, w = tid >> 5;
    const int gr = lane >> 2, gc = lane & 3;
    const int q0 = qt * 64;
    const int rs = 3 * C_;
    const float* base = qkv + (size_t)b * T_ * rs + h * DH_;
    const float scale = 0.125f;

    // ---- load Q tile (tf32) ----
    #pragma unroll
    for (int rr = 0; rr < 8; rr++) {
        int lin = tid + rr * 128;
        int row = lin >> 4, d4 = (lin & 15) * 4;
        float4 v = *(const float4*)(base + (size_t)(q0 + row) * rs + d4);
        uint4 u;
        u.x = f2tf(v.x); u.y = f2tf(v.y); u.z = f2tf(v.z); u.w = f2tf(v.w);
        *(uint4*)&Qs[row * PAD + d4] = u;
    }
    __syncthreads();

    const int mrowA = w * 16 + gr;

    float m0 = -1e30f, m1 = -1e30f, l0 = 0.f, l1 = 0.f;

    // ================= PASS 1: row statistics =================
    for (int kt = 0; kt <= qt; kt++) {
        #pragma unroll
        for (int rr = 0; rr < 8; rr++) {
            int lin = tid + rr * 128;
            int row = lin >> 4, d4 = (lin & 15) * 4;
            float4 v = *(const float4*)(base + C_ + (size_t)(kt * 64 + row) * rs + d4);
            uint4 u;
            u.x = f2tf(v.x); u.y = f2tf(v.y); u.z = f2tf(v.z); u.w = f2tf(v.w);
            *(uint4*)&Ks[row * PAD + d4] = u;
        }
        __syncthreads();

        float sf[8][4];
        #pragma unroll
        for (int nf = 0; nf < 8; nf++)
            #pragma unroll
            for (int i = 0; i < 4; i++) sf[nf][i] = 0.f;

        #pragma unroll
        for (int ks = 0; ks < 64; ks += 8) {
            uint32_t af[4];
            af[0] = Qs[(mrowA)     * PAD + ks + gc];
            af[1] = Qs[(mrowA + 8) * PAD + ks + gc];
            af[2] = Qs[(mrowA)     * PAD + ks + gc + 4];
            af[3] = Qs[(mrowA + 8) * PAD + ks + gc + 4];
            #pragma unroll
            for (int nf = 0; nf < 8; nf++) {
                uint32_t bf[2];
                bf[0] = Ks[(nf * 8 + gr) * PAD + ks + gc];
                bf[1] = Ks[(nf * 8 + gr) * PAD + ks + gc + 4];
                mma_tf32(sf[nf], af, bf);
            }
        }

        bool diag = (kt == qt);
        #pragma unroll
        for (int nf = 0; nf < 8; nf++)
            #pragma unroll
            for (int i = 0; i < 4; i++) {
                float v = sf[nf][i] * scale;
                int ml = w * 16 + gr + ((i >= 2) ? 8 : 0);
                int nl = nf * 8 + 2 * gc + (i & 1);
                if (diag && nl > ml) v = -1e30f;
                sf[nf][i] = v;
            }

        float tm0 = -1e30f, tm1 = -1e30f;
        #pragma unroll
        for (int nf = 0; nf < 8; nf++) {
            tm0 = fmaxf(tm0, fmaxf(sf[nf][0], sf[nf][1]));
            tm1 = fmaxf(tm1, fmaxf(sf[nf][2], sf[nf][3]));
        }
        tm0 = fmaxf(tm0, __shfl_xor_sync(0xffffffffu, tm0, 1));
        tm0 = fmaxf(tm0, __shfl_xor_sync(0xffffffffu, tm0, 2));
        tm1 = fmaxf(tm1, __shfl_xor_sync(0xffffffffu, tm1, 1));
        tm1 = fmaxf(tm1, __shfl_xor_sync(0xffffffffu, tm1, 2));
        float mn0 = fmaxf(m0, tm0), mn1 = fmaxf(m1, tm1);
        float s0 = 0.f, s1 = 0.f;
        #pragma unroll
        for (int nf = 0; nf < 8; nf++) {
            s0 += __expf(sf[nf][0] - mn0) + __expf(sf[nf][1] - mn0);
            s1 += __expf(sf[nf][2] - mn1) + __expf(sf[nf][3] - mn1);
        }
        s0 += __shfl_xor_sync(0xffffffffu, s0, 1);
        s0 += __shfl_xor_sync(0xffffffffu, s0, 2);
        s1 += __shfl_xor_sync(0xffffffffu, s1, 1);
        s1 += __shfl_xor_sync(0xffffffffu, s1, 2);
        l0 = l0 * __expf(m0 - mn0) + s0; m0 = mn0;
        l1 = l1 * __expf(m1 - mn1) + s1; m1 = mn1;
        __syncthreads();
    }

    float linv0 = 1.f / l0, linv1 = 1.f / l1;

    float yac[8][4];
    #pragma unroll
    for (int nf = 0; nf < 8; nf++)
        #pragma unroll
        for (int i = 0; i < 4; i++) yac[nf][i] = 0.f;

    // ================= PASS 2: att + y = P@V =================
    for (int kt = 0; kt <= qt; kt++) {
        #pragma unroll
        for (int rr = 0; rr < 8; rr++) {
            int lin = tid + rr * 128;
            int row = lin >> 4, d4 = (lin & 15) * 4;
            float4 vk = *(const float4*)(base + C_ + (size_t)(kt * 64 + row) * rs + d4);
            uint4 uk;
            uk.x = f2tf(vk.x); uk.y = f2tf(vk.y); uk.z = f2tf(vk.z); uk.w = f2tf(vk.w);
            *(uint4*)&Ks[row * PAD + d4] = uk;
            float4 vv = *(const float4*)(base + 2 * C_ + (size_t)(kt * 64 + row) * rs + d4);
            uint4 uv;
            uv.x = f2tf(vv.x); uv.y = f2tf(vv.y); uv.z = f2tf(vv.z); uv.w = f2tf(vv.w);
            *(uint4*)&Vs[row * PAD + d4] = uv;
        }
        __syncthreads();

        float sf[8][4];
        #pragma unroll
        for (int nf = 0; nf < 8; nf++)
            #pragma unroll
            for (int i = 0; i < 4; i++) sf[nf][i] = 0.f;

        #pragma unroll
        for (int ks = 0; ks < 64; ks += 8) {
            uint32_t af[4];
            af[0] = Qs[(mrowA)     * PAD + ks + gc];
            af[1] = Qs[(mrowA + 8) * PAD + ks + gc];
            af[2] = Qs[(mrowA)     * PAD + ks + gc + 4];
            af[3] = Qs[(mrowA + 8) * PAD + ks + gc + 4];
            #pragma unroll
            for (int nf = 0; nf < 8; nf++) {
                uint32_t bf[2];
                bf[0] = Ks[(nf * 8 + gr) * PAD + ks + gc];
                bf[1] = Ks[(nf * 8 + gr) * PAD + ks + gc + 4];
                mma_tf32(sf[nf], af, bf);
            }
        }

        bool diag = (kt == qt);
        #pragma unroll
        for (int nf = 0; nf < 8; nf++) {
            float p[4];
            #pragma unroll
            for (int i = 0; i < 4; i++) {
                int ml = w * 16 + gr + ((i >= 2) ? 8 : 0);
                int nl = nf * 8 + 2 * gc + (i & 1);
                float mm = (i >= 2) ? m1 : m0;
                float li = (i >= 2) ? linv1 : linv0;
                float pv = __expf(sf[nf][i] * scale - mm) * li;
                if (diag && nl > ml) pv = 0.f;
                p[i] = pv;
            }
            if (write_att) {
                size_t rb = ((size_t)bh * T_ + q0 + w * 16 + gr) * T_ + kt * 64 + nf * 8 + 2 * gc;
                *(float2*)(att + rb)            = make_float2(p[0], p[1]);
                *(float2*)(att + rb + 8 * T_)   = make_float2(p[2], p[3]);
            }
            uint2 u0; u0.x = f2tf(p[0]); u0.y = f2tf(p[1]);
            uint2 u1; u1.x = f2tf(p[2]); u1.y = f2tf(p[3]);
            *(uint2*)&Ps[(w * 16 + gr)     * PAD + nf * 8 + 2 * gc] = u0;
            *(uint2*)&Ps[(w * 16 + gr + 8) * PAD + nf * 8 + 2 * gc] = u1;
        }
        __syncwarp();

        #pragma unroll
        for (int ks = 0; ks < 64; ks += 8) {
            uint32_t af[4];
            af[0] = Ps[(mrowA)     * PAD + ks + gc];
            af[1] = Ps[(mrowA + 8) * PAD + ks + gc];
            af[2] = Ps[(mrowA)     * PAD + ks + gc + 4];
            af[3] = Ps[(mrowA + 8) * PAD + ks + gc + 4];
            #pragma unroll
            for (int nf = 0; nf < 8; nf++) {
                uint32_t bf[2];
                bf[0] = Vs[(ks + gc)     * PAD + nf * 8 + gr];
                bf[1] = Vs[(ks + gc + 4) * PAD + nf * 8 + gr];
                mma_tf32(yac[nf], af, bf);
            }
        }
        __syncthreads();
    }

    // ---- zero-fill causal upper triangle ----
    if (write_att) {
        float4 z = make_float4(0.f, 0.f, 0.f, 0.f);
        for (int kt = qt + 1; kt < T_ / 64; kt++) {
            #pragma unroll
            for (int rr = 0; rr < 8; rr++) {
                int lin = tid + rr * 128;
                int row = lin >> 4, c4 = (lin & 15) * 4;
                *(float4*)(att + ((size_t)bh * T_ + q0 + row) * T_ + kt * 64 + c4) = z;
            }
        }
    }

    // ---- write y ----
    #pragma unroll
    for (int nf = 0; nf < 8; nf++) {
        size_t rb = ((size_t)b * T_ + q0 + w * 16 + gr) * C_ + h * DH_ + nf * 8 + 2 * gc;
        *(float2*)(y + rb)          = make_float2(yac[nf][0], yac[nf][1]);
        *(float2*)(y + rb + 8 * C_) = make_float2(yac[nf][2], yac[nf][3]);
    }
}

// ---------------------------------------------------------------------------
extern "C" void kernel_launch(void* const* d_in, const int* in_sizes, int n_in,
                              void* d_out, int out_size)
{
    (void)in_sizes; (void)n_in;
    const float* x      = (const float*)d_in[0];
    const float* W_attn = (const float*)d_in[1];
    const float* b_attn = (const float*)d_in[2];
    const float* W_o    = (const float*)d_in[3];
    const float* b_o    = (const float*)d_in[4];
    const float* W_fc   = (const float*)d_in[5];
    const float* b_fc   = (const float*)d_in[6];
    const float* W_fc2  = (const float*)d_in[7];
    const float* b_fc2  = (const float*)d_in[8];
    const float* g1     = (const float*)d_in[9];
    const float* be1    = (const float*)d_in[10];
    const float* g2     = (const float*)d_in[11];
    const float* be2    = (const float*)d_in[12];
    float* out = (float*)d_out;

    float *h, *qkv, *y, *x1, *m;
    cudaGetSymbolAddress((void**)&h,   g_h);
    cudaGetSymbolAddress((void**)&qkv, g_qkv);
    cudaGetSymbolAddress((void**)&y,   g_y);
    cudaGetSymbolAddress((void**)&x1,  g_x1);
    cudaGetSymbolAddress((void**)&m,   g_m);

    int write_att = (out_size >= X_SIZE + ATT_SIZE) ? 1 : 0;
    float* att = out + X_SIZE;

    const int GEMM_SMEM = 4 * GSTG * 4;            // 69632 B
    const int ATTN_SMEM = 4 * 64 * PAD * 4;        // 69632 B
    cudaFuncSetAttribute(gemm_tc<0>, cudaFuncAttributeMaxDynamicSharedMemorySize, GEMM_SMEM);
    cudaFuncSetAttribute(gemm_tc<1>, cudaFuncAttributeMaxDynamicSharedMemorySize, GEMM_SMEM);
    cudaFuncSetAttribute(gemm_tc<2>, cudaFuncAttributeMaxDynamicSharedMemorySize, GEMM_SMEM);
    cudaFuncSetAttribute(attn_tc, cudaFuncAttributeMaxDynamicSharedMemorySize, ATTN_SMEM);

    // 1. h = LN1(x)
    ln_kernel<<<BT_, 256>>>(x, g1, be1, h);
    // 2. qkv = h @ W_attn + b_attn
    gemm_tc<0><<<dim3(3 * C_ / 128, BT_ / 128), 256, GEMM_SMEM>>>(h, W_attn, b_attn, nullptr, qkv, BT_, 3 * C_, C_);
    // 3. attention -> att (d_out) + y
    attn_tc<<<dim3(T_ / 64, B_ * H_), 128, ATTN_SMEM>>>(qkv, att, y, write_att);
    // 4. x1 = x + y @ W_o + b_o
    gemm_tc<1><<<dim3(C_ / 128, BT_ / 128), 256, GEMM_SMEM>>>(y, W_o, b_o, x, x1, BT_, C_, C_);
    // 5. h = LN2(x1)
    ln_kernel<<<BT_, 256>>>(x1, g2, be2, h);
    // 6. m = gelu(h @ W_fc + b_fc)
    gemm_tc<2><<<dim3(4 * C_ / 128, BT_ / 128), 256, GEMM_SMEM>>>(h, W_fc, b_fc, nullptr, m, BT_, 4 * C_, C_);
    // 7. out_x = x1 + m @ W_fc2 + b_fc2
    gemm_tc<1><<<dim3(C_ / 128, BT_ / 128), 256, GEMM_SMEM>>>(m, W_fc2, b_fc2, x1, out, BT_, C_, 4 * C_);
}

// round 5
// speedup vs baseline: 3.1948x; 1.2277x over previous
#include <cuda_runtime.h>
#include <math.h>
#include <stdint.h>

#define B_ 2
#define T_ 2048
#define C_ 1024
#define H_ 16
#define DH_ 64
#define BT_ (B_*T_)
#define X_SIZE (BT_*C_)
#define ATT_SIZE (B_*H_*T_*T_)

// Scratch (device globals: allocation-free per harness rules)
__device__ float g_h[BT_ * C_];
__device__ float g_qkv[BT_ * 3 * C_];
__device__ float g_y[BT_ * C_];
__device__ float g_x1[BT_ * C_];
__device__ float g_m[BT_ * 4 * C_];
// tf32-rounded weights
__device__ float g_wattn[C_ * 3 * C_];
__device__ float g_wo[C_ * C_];
__device__ float g_wfc[C_ * 4 * C_];
__device__ float g_wfc2[4 * C_ * C_];

// ---------------------------------------------------------------------------
__device__ __forceinline__ uint32_t f2tf(float f) {
    uint32_t u;
    asm("cvt.rna.tf32.f32 %0, %1;" : "=r"(u) : "f"(f));
    return u;
}
__device__ __forceinline__ float f2tf_f(float f) { return __uint_as_float(f2tf(f)); }

__device__ __forceinline__ void mma_tf32(float (&d)[4], const uint32_t (&a)[4],
                                         const uint32_t (&b)[2]) {
    asm volatile(
        "mma.sync.aligned.m16n8k8.row.col.f32.tf32.tf32.f32 "
        "{%0,%1,%2,%3}, {%4,%5,%6,%7}, {%8,%9}, {%0,%1,%2,%3};"
        : "+f"(d[0]), "+f"(d[1]), "+f"(d[2]), "+f"(d[3])
        : "r"(a[0]), "r"(a[1]), "r"(a[2]), "r"(a[3]), "r"(b[0]), "r"(b[1]));
}

__device__ __forceinline__ void cp16(uint32_t dst, const float* src) {
    asm volatile("cp.async.cg.shared.global [%0], [%1], 16;" :: "r"(dst), "l"(src));
}
#define CP_COMMIT() asm volatile("cp.async.commit_group;")
#define CP_WAIT(n)  asm volatile("cp.async.wait_group %0;" :: "n"(n))

// ---------------------------------------------------------------------------
// Weight pre-rounding to tf32 (rna), stored as fp32 bit patterns.
// ---------------------------------------------------------------------------
__global__ void __launch_bounds__(256) cvt_tf32_kernel(const float4* __restrict__ src,
                                                       float4* __restrict__ dst, int n4)
{
    int i = blockIdx.x * 256 + threadIdx.x;
    int stride = gridDim.x * 256;
    for (; i < n4; i += stride) {
        float4 v = src[i];
        v.x = f2tf_f(v.x); v.y = f2tf_f(v.y); v.z = f2tf_f(v.z); v.w = f2tf_f(v.w);
        dst[i] = v;
    }
}

// ---------------------------------------------------------------------------
// LayerNorm (outputs tf32-rna rounded; h feeds GEMM A operands only).
// ---------------------------------------------------------------------------
__global__ void __launch_bounds__(256) ln_kernel(const float* __restrict__ x,
                                                 const float* __restrict__ g,
                                                 const float* __restrict__ be,
                                                 float* __restrict__ out)
{
    int row = blockIdx.x;
    int tid = threadIdx.x;
    const float4* xr = (const float4*)(x + (size_t)row * C_);
    float4 v = xr[tid];
    float s  = v.x + v.y + v.z + v.w;
    float ss = v.x * v.x + v.y * v.y + v.z * v.z + v.w * v.w;
    #pragma unroll
    for (int m = 16; m; m >>= 1) {
        s  += __shfl_xor_sync(0xffffffffu, s,  m);
        ss += __shfl_xor_sync(0xffffffffu, ss, m);
    }
    __shared__ float sh_s[8], sh_ss[8];
    if ((tid & 31) == 0) { sh_s[tid >> 5] = s; sh_ss[tid >> 5] = ss; }
    __syncthreads();
    s = 0.f; ss = 0.f;
    #pragma unroll
    for (int i = 0; i < 8; i++) { s += sh_s[i]; ss += sh_ss[i]; }
    float mean = s * (1.f / C_);
    float var  = ss * (1.f / C_) - mean * mean;
    float rstd = rsqrtf(var + 1e-5f);
    float4 gg = ((const float4*)g)[tid];
    float4 bb = ((const float4*)be)[tid];
    float4 o;
    o.x = f2tf_f((v.x - mean) * rstd * gg.x + bb.x);
    o.y = f2tf_f((v.y - mean) * rstd * gg.y + bb.y);
    o.z = f2tf_f((v.z - mean) * rstd * gg.z + bb.z);
    o.w = f2tf_f((v.w - mean) * rstd * gg.w + bb.w);
    ((float4*)(out + (size_t)row * C_))[tid] = o;
}

// ---------------------------------------------------------------------------
// tf32 tensor-core GEMM, cp.async 4-stage pipeline, 2 CTAs/SM.
// 128x128 tile, BK=16, 256 threads (8 warps 2x4), warp tile 64x32.
// Operands are pre-rounded to tf32; raw bits fed to mma.
// A smem [m][k] stride 20 (conflict-free), B smem [k][n] stride 136.
// ---------------------------------------------------------------------------
#define ASTR 20
#define BSTR 136
#define A_STG (128 * ASTR)
#define B_STG (16 * BSTR)
#define NSTAGE 4
#define GEMM_SMEM_BYTES (NSTAGE * (A_STG + B_STG) * 4)

template <int EPI>
__global__ void __launch_bounds__(256, 2) gemm_tc(
    const float* __restrict__ A, const float* __restrict__ W,
    const float* __restrict__ bias, const float* __restrict__ R,
    float* __restrict__ Cout, int M, int N, int K)
{
    extern __shared__ float dsm[];
    float* sA = dsm;
    float* sB = dsm + NSTAGE * A_STG;
    uint32_t sA_u = (uint32_t)__cvta_generic_to_shared(sA);
    uint32_t sB_u = (uint32_t)__cvta_generic_to_shared(sB);

    const int tid  = threadIdx.x;
    const int lane = tid & 31;
    const int wid  = tid >> 5;
    const int wm   = (wid >> 2) * 64;
    const int wn   = (wid & 3) * 32;
    const int m0 = blockIdx.y * 128, n0 = blockIdx.x * 128;
    const int gr = lane >> 2, gc = lane & 3;

    // async-copy mapping
    const int caRow = tid >> 2, caC4 = tid & 3;    // A: 2 chunks (rows r, r+64)
    const int cbRow = tid >> 5, cbC4 = tid & 31;   // B: 2 chunks (rows r, r+8)
    const float* Abase = A + (size_t)(m0 + caRow) * K + caC4 * 4;
    const float* Bbase = W + (size_t)cbRow * N + n0 + cbC4 * 4;

    float acc[4][4][4];
    #pragma unroll
    for (int mt = 0; mt < 4; mt++)
        #pragma unroll
        for (int nt = 0; nt < 4; nt++)
            #pragma unroll
            for (int i = 0; i < 4; i++) acc[mt][nt][i] = 0.f;

    const int KT = K >> 4;

    auto issue = [&](int kt, int s) {
        uint32_t a_dst = sA_u + (uint32_t)(s * A_STG + caRow * ASTR + caC4 * 4) * 4;
        const float* a_src = Abase + kt * 16;
        cp16(a_dst, a_src);
        cp16(a_dst + 64 * ASTR * 4, a_src + (size_t)64 * K);
        uint32_t b_dst = sB_u + (uint32_t)(s * B_STG + cbRow * BSTR + cbC4 * 4) * 4;
        const float* b_src = Bbase + (size_t)kt * 16 * N;
        cp16(b_dst, b_src);
        cp16(b_dst + 8 * BSTR * 4, b_src + (size_t)8 * N);
    };

    #pragma unroll
    for (int s = 0; s < NSTAGE - 1; s++) {
        if (s < KT) issue(s, s);
        CP_COMMIT();
    }
    CP_WAIT(NSTAGE - 2);
    __syncthreads();

    for (int kt = 0; kt < KT; kt++) {
        const uint32_t* ua = (const uint32_t*)(sA + (kt & (NSTAGE - 1)) * A_STG);
        const uint32_t* ub = (const uint32_t*)(sB + (kt & (NSTAGE - 1)) * B_STG);
        #pragma unroll
        for (int ks = 0; ks < 16; ks += 8) {
            uint32_t af[4][4];
            #pragma unroll
            for (int mt = 0; mt < 4; mt++) {
                int mrow = wm + mt * 16 + gr;
                af[mt][0] = ua[(mrow)     * ASTR + ks + gc];
                af[mt][1] = ua[(mrow + 8) * ASTR + ks + gc];
                af[mt][2] = ua[(mrow)     * ASTR + ks + gc + 4];
                af[mt][3] = ua[(mrow + 8) * ASTR + ks + gc + 4];
            }
            uint32_t bf[4][2];
            #pragma unroll
            for (int nt = 0; nt < 4; nt++) {
                int ncol = wn + nt * 8 + gr;
                bf[nt][0] = ub[(ks + gc)     * BSTR + ncol];
                bf[nt][1] = ub[(ks + gc + 4) * BSTR + ncol];
            }
            #pragma unroll
            for (int mt = 0; mt < 4; mt++)
                #pragma unroll
                for (int nt = 0; nt < 4; nt++)
                    mma_tf32(acc[mt][nt], af[mt], bf[nt]);
        }
        int kn = kt + NSTAGE - 1;
        if (kn < KT) issue(kn, kn & (NSTAGE - 1));
        CP_COMMIT();
        CP_WAIT(NSTAGE - 2);
        __syncthreads();
    }

    // ---- epilogue ----
    #pragma unroll
    for (int nt = 0; nt < 4; nt++) {
        int col = n0 + wn + nt * 8 + (gc << 1);
        float bx = bias[col], by = bias[col + 1];
        #pragma unroll
        for (int mt = 0; mt < 4; mt++) {
            int row0 = m0 + wm + mt * 16 + gr;
            #pragma unroll
            for (int half = 0; half < 2; half++) {
                int row = row0 + half * 8;
                float vx = acc[mt][nt][half * 2 + 0] + bx;
                float vy = acc[mt][nt][half * 2 + 1] + by;
                if (EPI == 2) {
                    vx = f2tf_f(0.5f * vx * (1.0f + erff(vx * 0.70710678118654752f)));
                    vy = f2tf_f(0.5f * vy * (1.0f + erff(vy * 0.70710678118654752f)));
                }
                size_t off = (size_t)row * N + col;
                if (EPI == 1) {
                    vx += R[off];
                    vy += R[off + 1];
                }
                *(float2*)(Cout + off) = make_float2(vx, vy);
            }
        }
    }
}

// ---------------------------------------------------------------------------
// Tensor-core causal flash attention with exact 2-pass softmax.
// Block: 128 threads (4 warps), tile 64q x 64k, DH=64.
// ---------------------------------------------------------------------------
#define PAD 68

__global__ void __launch_bounds__(128) attn_tc(
    const float* __restrict__ qkv, float* __restrict__ att,
    float* __restrict__ y, int write_att)
{
    extern __shared__ uint32_t sm[];
    uint32_t* Qs = sm;               // [64][68]
    uint32_t* Ks = Qs + 64 * PAD;
    uint32_t* Vs = Ks + 64 * PAD;
    uint32_t* Ps = Vs + 64 * PAD;

    const int qt = blockIdx.x, bh = blockIdx.y;
    const int b = bh >> 4, h = bh & 15;
    const int tid = threadIdx.x;
    const int lane = tid & 31, w = tid >> 5;
    const int gr = lane >> 2, gc = lane & 3;
    const int q0 = qt * 64;
    const int rs = 3 * C_;
    const float* base = qkv + (size_t)b * T_ * rs + h * DH_;
    const float scale = 0.125f;

    #pragma unroll
    for (int rr = 0; rr < 8; rr++) {
        int lin = tid + rr * 128;
        int row = lin >> 4, d4 = (lin & 15) * 4;
        float4 v = *(const float4*)(base + (size_t)(q0 + row) * rs + d4);
        uint4 u;
        u.x = f2tf(v.x); u.y = f2tf(v.y); u.z = f2tf(v.z); u.w = f2tf(v.w);
        *(uint4*)&Qs[row * PAD + d4] = u;
    }
    __syncthreads();

    const int mrowA = w * 16 + gr;

    float m0 = -1e30f, m1 = -1e30f, l0 = 0.f, l1 = 0.f;

    // ================= PASS 1: row statistics =================
    for (int kt = 0; kt <= qt; kt++) {
        #pragma unroll
        for (int rr = 0; rr < 8; rr++) {
            int lin = tid + rr * 128;
            int row = lin >> 4, d4 = (lin & 15) * 4;
            float4 v = *(const float4*)(base + C_ + (size_t)(kt * 64 + row) * rs + d4);
            uint4 u;
            u.x = f2tf(v.x); u.y = f2tf(v.y); u.z = f2tf(v.z); u.w = f2tf(v.w);
            *(uint4*)&Ks[row * PAD + d4] = u;
        }
        __syncthreads();

        float sf[8][4];
        #pragma unroll
        for (int nf = 0; nf < 8; nf++)
            #pragma unroll
            for (int i = 0; i < 4; i++) sf[nf][i] = 0.f;

        #pragma unroll
        for (int ks = 0; ks < 64; ks += 8) {
            uint32_t af[4];
            af[0] = Qs[(mrowA)     * PAD + ks + gc];
            af[1] = Qs[(mrowA + 8) * PAD + ks + gc];
            af[2] = Qs[(mrowA)     * PAD + ks + gc + 4];
            af[3] = Qs[(mrowA + 8) * PAD + ks + gc + 4];
            #pragma unroll
            for (int nf = 0; nf < 8; nf++) {
                uint32_t bf[2];
                bf[0] = Ks[(nf * 8 + gr) * PAD + ks + gc];
                bf[1] = Ks[(nf * 8 + gr) * PAD + ks + gc + 4];
                mma_tf32(sf[nf], af, bf);
            }
        }

        bool diag = (kt == qt);
        #pragma unroll
        for (int nf = 0; nf < 8; nf++)
            #pragma unroll
            for (int i = 0; i < 4; i++) {
                float v = sf[nf][i] * scale;
                int ml = w * 16 + gr + ((i >= 2) ? 8 : 0);
                int nl = nf * 8 + 2 * gc + (i & 1);
                if (diag && nl > ml) v = -1e30f;
                sf[nf][i] = v;
            }

        float tm0 = -1e30f, tm1 = -1e30f;
        #pragma unroll
        for (int nf = 0; nf < 8; nf++) {
            tm0 = fmaxf(tm0, fmaxf(sf[nf][0], sf[nf][1]));
            tm1 = fmaxf(tm1, fmaxf(sf[nf][2], sf[nf][3]));
        }
        tm0 = fmaxf(tm0, __shfl_xor_sync(0xffffffffu, tm0, 1));
        tm0 = fmaxf(tm0, __shfl_xor_sync(0xffffffffu, tm0, 2));
        tm1 = fmaxf(tm1, __shfl_xor_sync(0xffffffffu, tm1, 1));
        tm1 = fmaxf(tm1, __shfl_xor_sync(0xffffffffu, tm1, 2));
        float mn0 = fmaxf(m0, tm0), mn1 = fmaxf(m1, tm1);
        float s0 = 0.f, s1 = 0.f;
        #pragma unroll
        for (int nf = 0; nf < 8; nf++) {
            s0 += __expf(sf[nf][0] - mn0) + __expf(sf[nf][1] - mn0);
            s1 += __expf(sf[nf][2] - mn1) + __expf(sf[nf][3] - mn1);
        }
        s0 += __shfl_xor_sync(0xffffffffu, s0, 1);
        s0 += __shfl_xor_sync(0xffffffffu, s0, 2);
        s1 += __shfl_xor_sync(0xffffffffu, s1, 1);
        s1 += __shfl_xor_sync(0xffffffffu, s1, 2);
        l0 = l0 * __expf(m0 - mn0) + s0; m0 = mn0;
        l1 = l1 * __expf(m1 - mn1) + s1; m1 = mn1;
        __syncthreads();
    }

    float linv0 = 1.f / l0, linv1 = 1.f / l1;

    float yac[8][4];
    #pragma unroll
    for (int nf = 0; nf < 8; nf++)
        #pragma unroll
        for (int i = 0; i < 4; i++) yac[nf][i] = 0.f;

    // ================= PASS 2: att + y = P@V =================
    for (int kt = 0; kt <= qt; kt++) {
        #pragma unroll
        for (int rr = 0; rr < 8; rr++) {
            int lin = tid + rr * 128;
            int row = lin >> 4, d4 = (lin & 15) * 4;
            float4 vk = *(const float4*)(base + C_ + (size_t)(kt * 64 + row) * rs + d4);
            uint4 uk;
            uk.x = f2tf(vk.x); uk.y = f2tf(vk.y); uk.z = f2tf(vk.z); uk.w = f2tf(vk.w);
            *(uint4*)&Ks[row * PAD + d4] = uk;
            float4 vv = *(const float4*)(base + 2 * C_ + (size_t)(kt * 64 + row) * rs + d4);
            uint4 uv;
            uv.x = f2tf(vv.x); uv.y = f2tf(vv.y); uv.z = f2tf(vv.z); uv.w = f2tf(vv.w);
            *(uint4*)&Vs[row * PAD + d4] = uv;
        }
        __syncthreads();

        float sf[8][4];
        #pragma unroll
        for (int nf = 0; nf < 8; nf++)
            #pragma unroll
            for (int i = 0; i < 4; i++) sf[nf][i] = 0.f;

        #pragma unroll
        for (int ks = 0; ks < 64; ks += 8) {
            uint32_t af[4];
            af[0] = Qs[(mrowA)     * PAD + ks + gc];
            af[1] = Qs[(mrowA + 8) * PAD + ks + gc];
            af[2] = Qs[(mrowA)     * PAD + ks + gc + 4];
            af[3] = Qs[(mrowA + 8) * PAD + ks + gc + 4];
            #pragma unroll
            for (int nf = 0; nf < 8; nf++) {
                uint32_t bf[2];
                bf[0] = Ks[(nf * 8 + gr) * PAD + ks + gc];
                bf[1] = Ks[(nf * 8 + gr) * PAD + ks + gc + 4];
                mma_tf32(sf[nf], af, bf);
            }
        }

        bool diag = (kt == qt);
        #pragma unroll
        for (int nf = 0; nf < 8; nf++) {
            float p[4];
            #pragma unroll
            for (int i = 0; i < 4; i++) {
                int ml = w * 16 + gr + ((i >= 2) ? 8 : 0);
                int nl = nf * 8 + 2 * gc + (i & 1);
                float mm = (i >= 2) ? m1 : m0;
                float li = (i >= 2) ? linv1 : linv0;
                float pv = __expf(sf[nf][i] * scale - mm) * li;
                if (diag && nl > ml) pv = 0.f;
                p[i] = pv;
            }
            if (write_att) {
                size_t rb = ((size_t)bh * T_ + q0 + w * 16 + gr) * T_ + kt * 64 + nf * 8 + 2 * gc;
                *(float2*)(att + rb)            = make_float2(p[0], p[1]);
                *(float2*)(att + rb + 8 * T_)   = make_float2(p[2], p[3]);
            }
            uint2 u0; u0.x = f2tf(p[0]); u0.y = f2tf(p[1]);
            uint2 u1; u1.x = f2tf(p[2]); u1.y = f2tf(p[3]);
            *(uint2*)&Ps[(w * 16 + gr)     * PAD + nf * 8 + 2 * gc] = u0;
            *(uint2*)&Ps[(w * 16 + gr + 8) * PAD + nf * 8 + 2 * gc] = u1;
        }
        __syncwarp();

        #pragma unroll
        for (int ks = 0; ks < 64; ks += 8) {
            uint32_t af[4];
            af[0] = Ps[(mrowA)     * PAD + ks + gc];
            af[1] = Ps[(mrowA + 8) * PAD + ks + gc];
            af[2] = Ps[(mrowA)     * PAD + ks + gc + 4];
            af[3] = Ps[(mrowA + 8) * PAD + ks + gc + 4];
            #pragma unroll
            for (int nf = 0; nf < 8; nf++) {
                uint32_t bf[2];
                bf[0] = Vs[(ks + gc)     * PAD + nf * 8 + gr];
                bf[1] = Vs[(ks + gc + 4) * PAD + nf * 8 + gr];
                mma_tf32(yac[nf], af, bf);
            }
        }
        __syncthreads();
    }

    if (write_att) {
        float4 z = make_float4(0.f, 0.f, 0.f, 0.f);
        for (int kt = qt + 1; kt < T_ / 64; kt++) {
            #pragma unroll
            for (int rr = 0; rr < 8; rr++) {
                int lin = tid + rr * 128;
                int row = lin >> 4, c4 = (lin & 15) * 4;
                *(float4*)(att + ((size_t)bh * T_ + q0 + row) * T_ + kt * 64 + c4) = z;
            }
        }
    }

    // ---- write y (tf32-rounded; y feeds GEMM A operand only) ----
    #pragma unroll
    for (int nf = 0; nf < 8; nf++) {
        size_t rb = ((size_t)b * T_ + q0 + w * 16 + gr) * C_ + h * DH_ + nf * 8 + 2 * gc;
        *(float2*)(y + rb)          = make_float2(f2tf_f(yac[nf][0]), f2tf_f(yac[nf][1]));
        *(float2*)(y + rb + 8 * C_) = make_float2(f2tf_f(yac[nf][2]), f2tf_f(yac[nf][3]));
    }
}

// ---------------------------------------------------------------------------
extern "C" void kernel_launch(void* const* d_in, const int* in_sizes, int n_in,
                              void* d_out, int out_size)
{
    (void)in_sizes; (void)n_in;
    const float* x      = (const float*)d_in[0];
    const float* W_attn = (const float*)d_in[1];
    const float* b_attn = (const float*)d_in[2];
    const float* W_o    = (const float*)d_in[3];
    const float* b_o    = (const float*)d_in[4];
    const float* W_fc   = (const float*)d_in[5];
    const float* b_fc   = (const float*)d_in[6];
    const float* W_fc2  = (const float*)d_in[7];
    const float* b_fc2  = (const float*)d_in[8];
    const float* g1     = (const float*)d_in[9];
    const float* be1    = (const float*)d_in[10];
    const float* g2     = (const float*)d_in[11];
    const float* be2    = (const float*)d_in[12];
    float* out = (float*)d_out;

    float *h, *qkv, *y, *x1, *m, *wa, *wo, *wf, *wf2;
    cudaGetSymbolAddress((void**)&h,   g_h);
    cudaGetSymbolAddress((void**)&qkv, g_qkv);
    cudaGetSymbolAddress((void**)&y,   g_y);
    cudaGetSymbolAddress((void**)&x1,  g_x1);
    cudaGetSymbolAddress((void**)&m,   g_m);
    cudaGetSymbolAddress((void**)&wa,  g_wattn);
    cudaGetSymbolAddress((void**)&wo,  g_wo);
    cudaGetSymbolAddress((void**)&wf,  g_wfc);
    cudaGetSymbolAddress((void**)&wf2, g_wfc2);

    int write_att = (out_size >= X_SIZE + ATT_SIZE) ? 1 : 0;
    float* att = out + X_SIZE;

    const int ATTN_SMEM = 4 * 64 * PAD * 4;
    cudaFuncSetAttribute(gemm_tc<0>, cudaFuncAttributeMaxDynamicSharedMemorySize, GEMM_SMEM_BYTES);
    cudaFuncSetAttribute(gemm_tc<1>, cudaFuncAttributeMaxDynamicSharedMemorySize, GEMM_SMEM_BYTES);
    cudaFuncSetAttribute(gemm_tc<2>, cudaFuncAttributeMaxDynamicSharedMemorySize, GEMM_SMEM_BYTES);
    cudaFuncSetAttribute(attn_tc, cudaFuncAttributeMaxDynamicSharedMemorySize, ATTN_SMEM);

    // 0. pre-round weights to tf32 (rna)
    cvt_tf32_kernel<<<592, 256>>>((const float4*)W_attn, (float4*)wa, C_ * 3 * C_ / 4);
    cvt_tf32_kernel<<<592, 256>>>((const float4*)W_o,    (float4*)wo, C_ * C_ / 4);
    cvt_tf32_kernel<<<592, 256>>>((const float4*)W_fc,   (float4*)wf, C_ * 4 * C_ / 4);
    cvt_tf32_kernel<<<592, 256>>>((const float4*)W_fc2,  (float4*)wf2, 4 * C_ * C_ / 4);

    // 1. h = LN1(x)  (tf32-rounded)
    ln_kernel<<<BT_, 256>>>(x, g1, be1, h);
    // 2. qkv = h @ W_attn + b_attn
    gemm_tc<0><<<dim3(3 * C_ / 128, BT_ / 128), 256, GEMM_SMEM_BYTES>>>(h, wa, b_attn, nullptr, qkv, BT_, 3 * C_, C_);
    // 3. attention -> att (d_out) + y
    attn_tc<<<dim3(T_ / 64, B_ * H_), 128, ATTN_SMEM>>>(qkv, att, y, write_att);
    // 4. x1 = x + y @ W_o + b_o
    gemm_tc<1><<<dim3(C_ / 128, BT_ / 128), 256, GEMM_SMEM_BYTES>>>(y, wo, b_o, x, x1, BT_, C_, C_);
    // 5. h = LN2(x1)  (tf32-rounded)
    ln_kernel<<<BT_, 256>>>(x1, g2, be2, h);
    // 6. m = gelu(h @ W_fc + b_fc)  (tf32-rounded)
    gemm_tc<2><<<dim3(4 * C_ / 128, BT_ / 128), 256, GEMM_SMEM_BYTES>>>(h, wf, b_fc, nullptr, m, BT_, 4 * C_, C_);
    // 7. out_x = x1 + m @ W_fc2 + b_fc2
    gemm_tc<1><<<dim3(C_ / 128, BT_ / 128), 256, GEMM_SMEM_BYTES>>>(m, wf2, b_fc2, x1, out, BT_, C_, 4 * C_);
}

// round 6
// speedup vs baseline: 3.4106x; 1.0676x over previous
#include <cuda_runtime.h>
#include <math.h>
#include <stdint.h>

#define B_ 2
#define T_ 2048
#define C_ 1024
#define H_ 16
#define DH_ 64
#define BT_ (B_*T_)
#define X_SIZE (BT_*C_)
#define ATT_SIZE (B_*H_*T_*T_)

// Scratch (device globals: allocation-free per harness rules)
__device__ float g_h[BT_ * C_];
__device__ float g_qkv[BT_ * 3 * C_];
__device__ float g_y[BT_ * C_];
__device__ float g_x1[BT_ * C_];
__device__ float g_m[BT_ * 4 * C_];
// tf32-rounded weights
__device__ float g_wattn[C_ * 3 * C_];
__device__ float g_wo[C_ * C_];
__device__ float g_wfc[C_ * 4 * C_];
__device__ float g_wfc2[4 * C_ * C_];

// ---------------------------------------------------------------------------
__device__ __forceinline__ uint32_t f2tf(float f) {
    uint32_t u;
    asm("cvt.rna.tf32.f32 %0, %1;" : "=r"(u) : "f"(f));
    return u;
}
__device__ __forceinline__ float f2tf_f(float f) { return __uint_as_float(f2tf(f)); }

__device__ __forceinline__ void mma_tf32(float (&d)[4], const uint32_t (&a)[4],
                                         const uint32_t (&b)[2]) {
    asm volatile(
        "mma.sync.aligned.m16n8k8.row.col.f32.tf32.tf32.f32 "
        "{%0,%1,%2,%3}, {%4,%5,%6,%7}, {%8,%9}, {%0,%1,%2,%3};"
        : "+f"(d[0]), "+f"(d[1]), "+f"(d[2]), "+f"(d[3])
        : "r"(a[0]), "r"(a[1]), "r"(a[2]), "r"(a[3]), "r"(b[0]), "r"(b[1]));
}

__device__ __forceinline__ void cp16(uint32_t dst, const float* src) {
    asm volatile("cp.async.cg.shared.global [%0], [%1], 16;" :: "r"(dst), "l"(src));
}
#define CP_COMMIT() asm volatile("cp.async.commit_group;")
#define CP_WAIT(n)  asm volatile("cp.async.wait_group %0;" :: "n"(n))

// ---------------------------------------------------------------------------
// Pre-round all 4 weight matrices to tf32 (rna) in one kernel.
// Segments (in float4): wa 786432 | wo 262144 | wf 1048576 | wf2 1048576
// ---------------------------------------------------------------------------
#define N4_WA 786432
#define N4_WO 262144
#define N4_WF 1048576
#define N4_WF2 1048576
#define N4_TOT (N4_WA + N4_WO + N4_WF + N4_WF2)

__global__ void __launch_bounds__(256) cvt_all_kernel(
    const float4* __restrict__ wa_s, const float4* __restrict__ wo_s,
    const float4* __restrict__ wf_s, const float4* __restrict__ wf2_s,
    float4* __restrict__ wa_d, float4* __restrict__ wo_d,
    float4* __restrict__ wf_d, float4* __restrict__ wf2_d)
{
    int i = blockIdx.x * 256 + threadIdx.x;
    int stride = gridDim.x * 256;
    for (; i < N4_TOT; i += stride) {
        const float4* s; float4* d; int j = i;
        if (j < N4_WA)                { s = wa_s;  d = wa_d; }
        else if ((j -= N4_WA) < N4_WO)  { s = wo_s;  d = wo_d; }
        else if ((j -= N4_WO) < N4_WF)  { s = wf_s;  d = wf_d; }
        else { j -= N4_WF;              s = wf2_s; d = wf2_d; }
        float4 v = s[j];
        v.x = f2tf_f(v.x); v.y = f2tf_f(v.y); v.z = f2tf_f(v.z); v.w = f2tf_f(v.w);
        d[j] = v;
    }
}

// ---------------------------------------------------------------------------
// LayerNorm (outputs tf32-rna rounded; h feeds GEMM A operands only).
// ---------------------------------------------------------------------------
__global__ void __launch_bounds__(256) ln_kernel(const float* __restrict__ x,
                                                 const float* __restrict__ g,
                                                 const float* __restrict__ be,
                                                 float* __restrict__ out)
{
    int row = blockIdx.x;
    int tid = threadIdx.x;
    const float4* xr = (const float4*)(x + (size_t)row * C_);
    float4 v = xr[tid];
    float s  = v.x + v.y + v.z + v.w;
    float ss = v.x * v.x + v.y * v.y + v.z * v.z + v.w * v.w;
    #pragma unroll
    for (int m = 16; m; m >>= 1) {
        s  += __shfl_xor_sync(0xffffffffu, s,  m);
        ss += __shfl_xor_sync(0xffffffffu, ss, m);
    }
    __shared__ float sh_s[8], sh_ss[8];
    if ((tid & 31) == 0) { sh_s[tid >> 5] = s; sh_ss[tid >> 5] = ss; }
    __syncthreads();
    s = 0.f; ss = 0.f;
    #pragma unroll
    for (int i = 0; i < 8; i++) { s += sh_s[i]; ss += sh_ss[i]; }
    float mean = s * (1.f / C_);
    float var  = ss * (1.f / C_) - mean * mean;
    float rstd = rsqrtf(var + 1e-5f);
    float4 gg = ((const float4*)g)[tid];
    float4 bb = ((const float4*)be)[tid];
    float4 o;
    o.x = f2tf_f((v.x - mean) * rstd * gg.x + bb.x);
    o.y = f2tf_f((v.y - mean) * rstd * gg.y + bb.y);
    o.z = f2tf_f((v.z - mean) * rstd * gg.z + bb.z);
    o.w = f2tf_f((v.w - mean) * rstd * gg.w + bb.w);
    ((float4*)(out + (size_t)row * C_))[tid] = o;
}

// ---------------------------------------------------------------------------
// tf32 tensor-core GEMM, cp.async 3-stage pipeline, BK=32, 2 CTAs/SM.
// 128x128 tile, 256 threads (8 warps 2x4), warp tile 64x32.
// A smem [m][k] stride 36, B smem [k][n] stride 136 (both conflict-free LDS).
// ---------------------------------------------------------------------------
#define ASTR 36
#define BSTR 136
#define A_STG (128 * ASTR)
#define B_STG (32 * BSTR)
#define NSTAGE 3
#define GEMM_SMEM_BYTES (NSTAGE * (A_STG + B_STG) * 4)

template <int EPI>
__global__ void __launch_bounds__(256, 2) gemm_tc(
    const float* __restrict__ A, const float* __restrict__ W,
    const float* __restrict__ bias, const float* __restrict__ R,
    float* __restrict__ Cout, int M, int N, int K)
{
    extern __shared__ float dsm[];
    float* sA = dsm;
    float* sB = dsm + NSTAGE * A_STG;
    uint32_t sA_u = (uint32_t)__cvta_generic_to_shared(sA);
    uint32_t sB_u = (uint32_t)__cvta_generic_to_shared(sB);

    const int tid  = threadIdx.x;
    const int lane = tid & 31;
    const int wid  = tid >> 5;
    const int wm   = (wid >> 2) * 64;
    const int wn   = (wid & 3) * 32;
    const int m0 = blockIdx.y * 128, n0 = blockIdx.x * 128;
    const int gr = lane >> 2, gc = lane & 3;

    float acc[4][4][4];
    #pragma unroll
    for (int mt = 0; mt < 4; mt++)
        #pragma unroll
        for (int nt = 0; nt < 4; nt++)
            #pragma unroll
            for (int i = 0; i < 4; i++) acc[mt][nt][i] = 0.f;

    const int KT = K >> 5;   // BK = 32

    auto issue = [&](int kt, int s) {
        #pragma unroll
        for (int i = 0; i < 4; i++) {
            int id = tid + i * 256;              // 1024 chunks of A
            int row = id >> 3, c4 = id & 7;
            cp16(sA_u + (uint32_t)(s * A_STG + row * ASTR + c4 * 4) * 4,
                 A + (size_t)(m0 + row) * K + kt * 32 + c4 * 4);
        }
        #pragma unroll
        for (int i = 0; i < 4; i++) {
            int id = tid + i * 256;              // 1024 chunks of B
            int row = id >> 5, c4 = id & 31;
            cp16(sB_u + (uint32_t)(s * B_STG + row * BSTR + c4 * 4) * 4,
                 W + (size_t)(kt * 32 + row) * N + n0 + c4 * 4);
        }
    };

    issue(0, 0); CP_COMMIT();
    if (KT > 1) issue(1, 1);
    CP_COMMIT();
    CP_WAIT(1);
    __syncthreads();

    int s = 0;
    for (int kt = 0; kt < KT; kt++) {
        const uint32_t* ua = (const uint32_t*)(sA + s * A_STG);
        const uint32_t* ub = (const uint32_t*)(sB + s * B_STG);
        #pragma unroll
        for (int ks = 0; ks < 32; ks += 8) {
            uint32_t af[4][4];
            #pragma unroll
            for (int mt = 0; mt < 4; mt++) {
                int mrow = wm + mt * 16 + gr;
                af[mt][0] = ua[(mrow)     * ASTR + ks + gc];
                af[mt][1] = ua[(mrow + 8) * ASTR + ks + gc];
                af[mt][2] = ua[(mrow)     * ASTR + ks + gc + 4];
                af[mt][3] = ua[(mrow + 8) * ASTR + ks + gc + 4];
            }
            uint32_t bf[4][2];
            #pragma unroll
            for (int nt = 0; nt < 4; nt++) {
                int ncol = wn + nt * 8 + gr;
                bf[nt][0] = ub[(ks + gc)     * BSTR + ncol];
                bf[nt][1] = ub[(ks + gc + 4) * BSTR + ncol];
            }
            #pragma unroll
            for (int mt = 0; mt < 4; mt++)
                #pragma unroll
                for (int nt = 0; nt < 4; nt++)
                    mma_tf32(acc[mt][nt], af[mt], bf[nt]);
        }
        int kn = kt + 2;
        int sn = s + 2; if (sn >= NSTAGE) sn -= NSTAGE;
        if (kn < KT) issue(kn, sn);
        CP_COMMIT();
        CP_WAIT(1);
        __syncthreads();
        if (++s == NSTAGE) s = 0;
    }

    // ---- epilogue ----
    #pragma unroll
    for (int nt = 0; nt < 4; nt++) {
        int col = n0 + wn + nt * 8 + (gc << 1);
        float bx = bias[col], by = bias[col + 1];
        #pragma unroll
        for (int mt = 0; mt < 4; mt++) {
            int row0 = m0 + wm + mt * 16 + gr;
            #pragma unroll
            for (int half = 0; half < 2; half++) {
                int row = row0 + half * 8;
                float vx = acc[mt][nt][half * 2 + 0] + bx;
                float vy = acc[mt][nt][half * 2 + 1] + by;
                if (EPI == 2) {
                    vx = f2tf_f(0.5f * vx * (1.0f + erff(vx * 0.70710678118654752f)));
                    vy = f2tf_f(0.5f * vy * (1.0f + erff(vy * 0.70710678118654752f)));
                }
                size_t off = (size_t)row * N + col;
                if (EPI == 1) {
                    vx += R[off];
                    vy += R[off + 1];
                }
                *(float2*)(Cout + off) = make_float2(vx, vy);
            }
        }
    }
}

// ---------------------------------------------------------------------------
// Tensor-core causal flash attention with exact 2-pass softmax.
// Block: 128 threads (4 warps), tile 64q x 64k, DH=64.
// Q/K/V fed to mma as raw fp32 bits (HW tf32 truncation); P is rna-rounded.
// ---------------------------------------------------------------------------
#define PAD 68

__global__ void __launch_bounds__(128) attn_tc(
    const float* __restrict__ qkv, float* __restrict__ att,
    float* __restrict__ y, int write_att)
{
    extern __shared__ uint32_t sm[];
    uint32_t* Qs = sm;               // [64][68]
    uint32_t* Ks = Qs + 64 * PAD;
    uint32_t* Vs = Ks + 64 * PAD;
    uint32_t* Ps = Vs + 64 * PAD;

    const int qt = gridDim.x - 1 - blockIdx.x;   // heaviest tiles first
    const int bh = blockIdx.y;
    const int b = bh >> 4, h = bh & 15;
    const int tid = threadIdx.x;
    const int lane = tid & 31, w = tid >> 5;
    const int gr = lane >> 2, gc = lane & 3;
    const int q0 = qt * 64;
    const int rs = 3 * C_;
    const float* base = qkv + (size_t)b * T_ * rs + h * DH_;
    const float scale = 0.125f;

    #pragma unroll
    for (int rr = 0; rr < 8; rr++) {
        int lin = tid + rr * 128;
        int row = lin >> 4, d4 = (lin & 15) * 4;
        float4 v = *(const float4*)(base + (size_t)(q0 + row) * rs + d4);
        *(uint4*)&Qs[row * PAD + d4] = *(uint4*)&v;
    }
    __syncthreads();

    const int mrowA = w * 16 + gr;

    float m0 = -1e30f, m1 = -1e30f, l0 = 0.f, l1 = 0.f;

    // ================= PASS 1: row statistics =================
    for (int kt = 0; kt <= qt; kt++) {
        #pragma unroll
        for (int rr = 0; rr < 8; rr++) {
            int lin = tid + rr * 128;
            int row = lin >> 4, d4 = (lin & 15) * 4;
            float4 v = *(const float4*)(base + C_ + (size_t)(kt * 64 + row) * rs + d4);
            *(uint4*)&Ks[row * PAD + d4] = *(uint4*)&v;
        }
        __syncthreads();

        float sf[8][4];
        #pragma unroll
        for (int nf = 0; nf < 8; nf++)
            #pragma unroll
            for (int i = 0; i < 4; i++) sf[nf][i] = 0.f;

        #pragma unroll
        for (int ks = 0; ks < 64; ks += 8) {
            uint32_t af[4];
            af[0] = Qs[(mrowA)     * PAD + ks + gc];
            af[1] = Qs[(mrowA + 8) * PAD + ks + gc];
            af[2] = Qs[(mrowA)     * PAD + ks + gc + 4];
            af[3] = Qs[(mrowA + 8) * PAD + ks + gc + 4];
            #pragma unroll
            for (int nf = 0; nf < 8; nf++) {
                uint32_t bf[2];
                bf[0] = Ks[(nf * 8 + gr) * PAD + ks + gc];
                bf[1] = Ks[(nf * 8 + gr) * PAD + ks + gc + 4];
                mma_tf32(sf[nf], af, bf);
            }
        }

        bool diag = (kt == qt);
        #pragma unroll
        for (int nf = 0; nf < 8; nf++)
            #pragma unroll
            for (int i = 0; i < 4; i++) {
                float v = sf[nf][i] * scale;
                int ml = w * 16 + gr + ((i >= 2) ? 8 : 0);
                int nl = nf * 8 + 2 * gc + (i & 1);
                if (diag && nl > ml) v = -1e30f;
                sf[nf][i] = v;
            }

        float tm0 = -1e30f, tm1 = -1e30f;
        #pragma unroll
        for (int nf = 0; nf < 8; nf++) {
            tm0 = fmaxf(tm0, fmaxf(sf[nf][0], sf[nf][1]));
            tm1 = fmaxf(tm1, fmaxf(sf[nf][2], sf[nf][3]));
        }
        tm0 = fmaxf(tm0, __shfl_xor_sync(0xffffffffu, tm0, 1));
        tm0 = fmaxf(tm0, __shfl_xor_sync(0xffffffffu, tm0, 2));
        tm1 = fmaxf(tm1, __shfl_xor_sync(0xffffffffu, tm1, 1));
        tm1 = fmaxf(tm1, __shfl_xor_sync(0xffffffffu, tm1, 2));
        float mn0 = fmaxf(m0, tm0), mn1 = fmaxf(m1, tm1);
        float s0 = 0.f, s1 = 0.f;
        #pragma unroll
        for (int nf = 0; nf < 8; nf++) {
            s0 += __expf(sf[nf][0] - mn0) + __expf(sf[nf][1] - mn0);
            s1 += __expf(sf[nf][2] - mn1) + __expf(sf[nf][3] - mn1);
        }
        s0 += __shfl_xor_sync(0xffffffffu, s0, 1);
        s0 += __shfl_xor_sync(0xffffffffu, s0, 2);
        s1 += __shfl_xor_sync(0xffffffffu, s1, 1);
        s1 += __shfl_xor_sync(0xffffffffu, s1, 2);
        l0 = l0 * __expf(m0 - mn0) + s0; m0 = mn0;
        l1 = l1 * __expf(m1 - mn1) + s1; m1 = mn1;
        __syncthreads();
    }

    float linv0 = 1.f / l0, linv1 = 1.f / l1;

    float yac[8][4];
    #pragma unroll
    for (int nf = 0; nf < 8; nf++)
        #pragma unroll
        for (int i = 0; i < 4; i++) yac[nf][i] = 0.f;

    // ================= PASS 2: att + y = P@V =================
    for (int kt = 0; kt <= qt; kt++) {
        #pragma unroll
        for (int rr = 0; rr < 8; rr++) {
            int lin = tid + rr * 128;
            int row = lin >> 4, d4 = (lin & 15) * 4;
            float4 vk = *(const float4*)(base + C_ + (size_t)(kt * 64 + row) * rs + d4);
            *(uint4*)&Ks[row * PAD + d4] = *(uint4*)&vk;
            float4 vv = *(const float4*)(base + 2 * C_ + (size_t)(kt * 64 + row) * rs + d4);
            *(uint4*)&Vs[row * PAD + d4] = *(uint4*)&vv;
        }
        __syncthreads();

        float sf[8][4];
        #pragma unroll
        for (int nf = 0; nf < 8; nf++)
            #pragma unroll
            for (int i = 0; i < 4; i++) sf[nf][i] = 0.f;

        #pragma unroll
        for (int ks = 0; ks < 64; ks += 8) {
            uint32_t af[4];
            af[0] = Qs[(mrowA)     * PAD + ks + gc];
            af[1] = Qs[(mrowA + 8) * PAD + ks + gc];
            af[2] = Qs[(mrowA)     * PAD + ks + gc + 4];
            af[3] = Qs[(mrowA + 8) * PAD + ks + gc + 4];
            #pragma unroll
            for (int nf = 0; nf < 8; nf++) {
                uint32_t bf[2];
                bf[0] = Ks[(nf * 8 + gr) * PAD + ks + gc];
                bf[1] = Ks[(nf * 8 + gr) * PAD + ks + gc + 4];
                mma_tf32(sf[nf], af, bf);
            }
        }

        bool diag = (kt == qt);
        #pragma unroll
        for (int nf = 0; nf < 8; nf++) {
            float p[4];
            #pragma unroll
            for (int i = 0; i < 4; i++) {
                int ml = w * 16 + gr + ((i >= 2) ? 8 : 0);
                int nl = nf * 8 + 2 * gc + (i & 1);
                float mm = (i >= 2) ? m1 : m0;
                float li = (i >= 2) ? linv1 : linv0;
                float pv = __expf(sf[nf][i] * scale - mm) * li;
                if (diag && nl > ml) pv = 0.f;
                p[i] = pv;
            }
            if (write_att) {
                size_t rb = ((size_t)bh * T_ + q0 + w * 16 + gr) * T_ + kt * 64 + nf * 8 + 2 * gc;
                *(float2*)(att + rb)            = make_float2(p[0], p[1]);
                *(float2*)(att + rb + 8 * T_)   = make_float2(p[2], p[3]);
            }
            uint2 u0; u0.x = f2tf(p[0]); u0.y = f2tf(p[1]);
            uint2 u1; u1.x = f2tf(p[2]); u1.y = f2tf(p[3]);
            *(uint2*)&Ps[(w * 16 + gr)     * PAD + nf * 8 + 2 * gc] = u0;
            *(uint2*)&Ps[(w * 16 + gr + 8) * PAD + nf * 8 + 2 * gc] = u1;
        }
        __syncwarp();

        #pragma unroll
        for (int ks = 0; ks < 64; ks += 8) {
            uint32_t af[4];
            af[0] = Ps[(mrowA)     * PAD + ks + gc];
            af[1] = Ps[(mrowA + 8) * PAD + ks + gc];
            af[2] = Ps[(mrowA)     * PAD + ks + gc + 4];
            af[3] = Ps[(mrowA + 8) * PAD + ks + gc + 4];
            #pragma unroll
            for (int nf = 0; nf < 8; nf++) {
                uint32_t bf[2];
                bf[0] = Vs[(ks + gc)     * PAD + nf * 8 + gr];
                bf[1] = Vs[(ks + gc + 4) * PAD + nf * 8 + gr];
                mma_tf32(yac[nf], af, bf);
            }
        }
        __syncthreads();
    }

    if (write_att) {
        float4 z = make_float4(0.f, 0.f, 0.f, 0.f);
        for (int kt = qt + 1; kt < T_ / 64; kt++) {
            #pragma unroll
            for (int rr = 0; rr < 8; rr++) {
                int lin = tid + rr * 128;
                int row = lin >> 4, c4 = (lin & 15) * 4;
                *(float4*)(att + ((size_t)bh * T_ + q0 + row) * T_ + kt * 64 + c4) = z;
            }
        }
    }

    // ---- write y (tf32-rounded; y feeds GEMM A operand only) ----
    #pragma unroll
    for (int nf = 0; nf < 8; nf++) {
        size_t rb = ((size_t)b * T_ + q0 + w * 16 + gr) * C_ + h * DH_ + nf * 8 + 2 * gc;
        *(float2*)(y + rb)          = make_float2(f2tf_f(yac[nf][0]), f2tf_f(yac[nf][1]));
        *(float2*)(y + rb + 8 * C_) = make_float2(f2tf_f(yac[nf][2]), f2tf_f(yac[nf][3]));
    }
}

// ---------------------------------------------------------------------------
extern "C" void kernel_launch(void* const* d_in, const int* in_sizes, int n_in,
                              void* d_out, int out_size)
{
    (void)in_sizes; (void)n_in;
    const float* x      = (const float*)d_in[0];
    const float* W_attn = (const float*)d_in[1];
    const float* b_attn = (const float*)d_in[2];
    const float* W_o    = (const float*)d_in[3];
    const float* b_o    = (const float*)d_in[4];
    const float* W_fc   = (const float*)d_in[5];
    const float* b_fc   = (const float*)d_in[6];
    const float* W_fc2  = (const float*)d_in[7];
    const float* b_fc2  = (const float*)d_in[8];
    const float* g1     = (const float*)d_in[9];
    const float* be1    = (const float*)d_in[10];
    const float* g2     = (const float*)d_in[11];
    const float* be2    = (const float*)d_in[12];
    float* out = (float*)d_out;

    float *h, *qkv, *y, *x1, *m, *wa, *wo, *wf, *wf2;
    cudaGetSymbolAddress((void**)&h,   g_h);
    cudaGetSymbolAddress((void**)&qkv, g_qkv);
    cudaGetSymbolAddress((void**)&y,   g_y);
    cudaGetSymbolAddress((void**)&x1,  g_x1);
    cudaGetSymbolAddress((void**)&m,   g_m);
    cudaGetSymbolAddress((void**)&wa,  g_wattn);
    cudaGetSymbolAddress((void**)&wo,  g_wo);
    cudaGetSymbolAddress((void**)&wf,  g_wfc);
    cudaGetSymbolAddress((void**)&wf2, g_wfc2);

    int write_att = (out_size >= X_SIZE + ATT_SIZE) ? 1 : 0;
    float* att = out + X_SIZE;

    const int ATTN_SMEM = 4 * 64 * PAD * 4;
    cudaFuncSetAttribute(gemm_tc<0>, cudaFuncAttributeMaxDynamicSharedMemorySize, GEMM_SMEM_BYTES);
    cudaFuncSetAttribute(gemm_tc<1>, cudaFuncAttributeMaxDynamicSharedMemorySize, GEMM_SMEM_BYTES);
    cudaFuncSetAttribute(gemm_tc<2>, cudaFuncAttributeMaxDynamicSharedMemorySize, GEMM_SMEM_BYTES);
    cudaFuncSetAttribute(attn_tc, cudaFuncAttributeMaxDynamicSharedMemorySize, ATTN_SMEM);

    // 0. pre-round weights to tf32 (rna) — single fused kernel
    cvt_all_kernel<<<1184, 256>>>((const float4*)W_attn, (const float4*)W_o,
                                  (const float4*)W_fc, (const float4*)W_fc2,
                                  (float4*)wa, (float4*)wo, (float4*)wf, (float4*)wf2);

    // 1. h = LN1(x)  (tf32-rounded)
    ln_kernel<<<BT_, 256>>>(x, g1, be1, h);
    // 2. qkv = h @ W_attn + b_attn
    gemm_tc<0><<<dim3(3 * C_ / 128, BT_ / 128), 256, GEMM_SMEM_BYTES>>>(h, wa, b_attn, nullptr, qkv, BT_, 3 * C_, C_);
    // 3. attention -> att (d_out) + y
    attn_tc<<<dim3(T_ / 64, B_ * H_), 128, ATTN_SMEM>>>(qkv, att, y, write_att);
    // 4. x1 = x + y @ W_o + b_o
    gemm_tc<1><<<dim3(C_ / 128, BT_ / 128), 256, GEMM_SMEM_BYTES>>>(y, wo, b_o, x, x1, BT_, C_, C_);
    // 5. h = LN2(x1)  (tf32-rounded)
    ln_kernel<<<BT_, 256>>>(x1, g2, be2, h);
    // 6. m = gelu(h @ W_fc + b_fc)  (tf32-rounded)
    gemm_tc<2><<<dim3(4 * C_ / 128, BT_ / 128), 256, GEMM_SMEM_BYTES>>>(h, wf, b_fc, nullptr, m, BT_, 4 * C_, C_);
    // 7. out_x = x1 + m @ W_fc2 + b_fc2
    gemm_tc<1><<<dim3(C_ / 128, BT_ / 128), 256, GEMM_SMEM_BYTES>>>(m, wf2, b_fc2, x1, out, BT_, C_, 4 * C_);
}